// round 2
// baseline (speedup 1.0000x reference)
#include <cuda_runtime.h>
#include <math.h>

#define BATCH 16
#define SEQ   2048
#define DMODEL 1024
#define HDIM  64
#define NQKV  192   // q|k|v fused columns

// scratch for fused q,k,v: [B*S][192]
__device__ float g_qkv[(size_t)BATCH * SEQ * NQKV];

// ---------------------------------------------------------------------------
// Kernel 1: fused QKV projection.
//   out[row][0:64]=q, [64:128]=k, [128:192]=v   (bias added)
// grid = B*S/64 blocks, 256 threads. Thread (ty,tx) with ty=tid/16, tx=tid%16
// computes a 4x12 micro-tile of the 64x192 block output.
// ---------------------------------------------------------------------------
__global__ __launch_bounds__(256) void qkv_kernel(
    const float* __restrict__ x,
    const float* __restrict__ Wq, const float* __restrict__ bq,
    const float* __restrict__ Wk, const float* __restrict__ bk,
    const float* __restrict__ Wv, const float* __restrict__ bv)
{
    __shared__ float sx[64][33];       // x tile, padded (reads are warp-broadcast)
    __shared__ float sw[32][NQKV];     // W tile (q|k|v)
    __shared__ float sbias[NQKV];

    const int tid = threadIdx.x;
    const int ty = tid >> 4;          // 0..15
    const int tx = tid & 15;          // 0..15
    const int m0 = blockIdx.x * 64;

    if (tid < 64) {
        sbias[tid]       = bq[tid];
        sbias[64 + tid]  = bk[tid];
        sbias[128 + tid] = bv[tid];
    }

    float acc[4][12];
#pragma unroll
    for (int r = 0; r < 4; r++)
#pragma unroll
        for (int c = 0; c < 12; c++) acc[r][c] = 0.f;

    for (int k0 = 0; k0 < DMODEL; k0 += 32) {
        // ---- load x tile: 64 rows x 32 cols = 512 float4, 2 per thread ----
#pragma unroll
        for (int i = 0; i < 2; i++) {
            int id  = tid + i * 256;          // float4 id within tile
            int row = id >> 3;                // /8 float4 per row
            int c4  = id & 7;
            float4 v = *(const float4*)&x[(size_t)(m0 + row) * DMODEL + k0 + c4 * 4];
            sx[row][c4 * 4 + 0] = v.x;
            sx[row][c4 * 4 + 1] = v.y;
            sx[row][c4 * 4 + 2] = v.z;
            sx[row][c4 * 4 + 3] = v.w;
        }
        // ---- load W tile: 32 rows x 192 cols = 1536 float4, 6 per thread ----
#pragma unroll
        for (int i = 0; i < 6; i++) {
            int id  = tid + i * 256;
            int row = id / 48;
            int c4  = id % 48;
            int m   = c4 >> 4;                 // 0=q, 1=k, 2=v
            int lc  = (c4 & 15) * 4;
            const float* Wsrc = (m == 0) ? Wq : ((m == 1) ? Wk : Wv);
            float4 v = *(const float4*)&Wsrc[(size_t)(k0 + row) * HDIM + lc];
            *(float4*)&sw[row][c4 * 4] = v;
        }
        __syncthreads();

#pragma unroll 8
        for (int kk = 0; kk < 32; kk++) {
            float a0 = sx[ty * 4 + 0][kk];
            float a1 = sx[ty * 4 + 1][kk];
            float a2 = sx[ty * 4 + 2][kk];
            float a3 = sx[ty * 4 + 3][kk];
            float bb[12];
            *(float4*)&bb[0] = *(float4*)&sw[kk][tx * 12 + 0];
            *(float4*)&bb[4] = *(float4*)&sw[kk][tx * 12 + 4];
            *(float4*)&bb[8] = *(float4*)&sw[kk][tx * 12 + 8];
#pragma unroll
            for (int c = 0; c < 12; c++) {
                acc[0][c] += a0 * bb[c];
                acc[1][c] += a1 * bb[c];
                acc[2][c] += a2 * bb[c];
                acc[3][c] += a3 * bb[c];
            }
        }
        __syncthreads();
    }

#pragma unroll
    for (int r = 0; r < 4; r++) {
        size_t rowbase = (size_t)(m0 + ty * 4 + r) * NQKV;
#pragma unroll
        for (int c = 0; c < 12; c++) {
            int g = tx * 12 + c;
            g_qkv[rowbase + g] = acc[r][c] + sbias[g];
        }
    }
}

// ---------------------------------------------------------------------------
// Kernel 2: causal flash attention, fp32, HD=64.
// grid = (32 q-tiles, 16 batches), 256 threads. 64x64 q/kv tiles,
// 4x4 register micro-tiles, online softmax via width-16 shuffles.
// ---------------------------------------------------------------------------
#define SQT_STRIDE 65
#define SKT_STRIDE 65
#define SV_STRIDE  64
#define SP_STRIDE  72
#define ATT_SMEM ((64*SQT_STRIDE + 64*SKT_STRIDE + 64*SV_STRIDE + 64*SP_STRIDE) * (int)sizeof(float))

__global__ __launch_bounds__(256) void attn_kernel(float* __restrict__ out)
{
    extern __shared__ float smem[];
    float (*sqT)[SQT_STRIDE] = (float(*)[SQT_STRIDE])smem;                       // [d][i] Q^T
    float (*skT)[SKT_STRIDE] = (float(*)[SKT_STRIDE])(smem + 64 * SQT_STRIDE);   // [d][j] K^T
    float (*sv)[SV_STRIDE]   = (float(*)[SV_STRIDE])(smem + 64 * (SQT_STRIDE + SKT_STRIDE)); // [j][h]
    float (*sp)[SP_STRIDE]   = (float(*)[SP_STRIDE])(smem + 64 * (SQT_STRIDE + SKT_STRIDE + SV_STRIDE)); // [i][j]

    const int tid = threadIdx.x;
    const int ty = tid >> 4;     // row group
    const int tx = tid & 15;     // col group
    const int b  = blockIdx.y;
    const int qi = (int)gridDim.x - 1 - (int)blockIdx.x;   // long blocks first
    const int q0 = qi * 64;
    const size_t base = (size_t)b * SEQ * NQKV;

    // scale folded into exp2 domain: exp(s/sqrt(64)) = 2^(s * 0.125 * log2(e))
    const float scale2 = 0.125f * 1.4426950408889634f;

    // ---- load Q tile transposed ----
#pragma unroll
    for (int i = 0; i < 4; i++) {
        int id  = tid + i * 256;
        int row = id >> 4;
        int d4  = (id & 15) * 4;
        float4 v = *(const float4*)&g_qkv[base + (size_t)(q0 + row) * NQKV + d4];
        sqT[d4 + 0][row] = v.x;
        sqT[d4 + 1][row] = v.y;
        sqT[d4 + 2][row] = v.z;
        sqT[d4 + 3][row] = v.w;
    }

    float o[4][4];
    float m_run[4], l_run[4];
#pragma unroll
    for (int r = 0; r < 4; r++) {
        m_run[r] = -1e30f;
        l_run[r] = 0.f;
#pragma unroll
        for (int c = 0; c < 4; c++) o[r][c] = 0.f;
    }

    for (int j = 0; j <= qi; j++) {
        const int k0 = j * 64;
        __syncthreads();   // prior PV reads done (also covers initial sqT fill)

        // ---- load K tile (transposed) + V tile ----
#pragma unroll
        for (int i = 0; i < 4; i++) {
            int id  = tid + i * 256;
            int row = id >> 4;
            int d4  = (id & 15) * 4;
            const float* src = &g_qkv[base + (size_t)(k0 + row) * NQKV];
            float4 kv = *(const float4*)&src[64 + d4];
            skT[d4 + 0][row] = kv.x;
            skT[d4 + 1][row] = kv.y;
            skT[d4 + 2][row] = kv.z;
            skT[d4 + 3][row] = kv.w;
            *(float4*)&sv[row][d4] = *(const float4*)&src[128 + d4];
        }
        __syncthreads();

        // ---- S = Q K^T (4x4 micro-tile) ----
        float s[4][4];
#pragma unroll
        for (int r = 0; r < 4; r++)
#pragma unroll
            for (int c = 0; c < 4; c++) s[r][c] = 0.f;

#pragma unroll 8
        for (int d = 0; d < 64; d++) {
            float qf0 = sqT[d][ty * 4 + 0];
            float qf1 = sqT[d][ty * 4 + 1];
            float qf2 = sqT[d][ty * 4 + 2];
            float qf3 = sqT[d][ty * 4 + 3];
            float kf0 = skT[d][tx * 4 + 0];
            float kf1 = skT[d][tx * 4 + 1];
            float kf2 = skT[d][tx * 4 + 2];
            float kf3 = skT[d][tx * 4 + 3];
            s[0][0] += qf0 * kf0; s[0][1] += qf0 * kf1; s[0][2] += qf0 * kf2; s[0][3] += qf0 * kf3;
            s[1][0] += qf1 * kf0; s[1][1] += qf1 * kf1; s[1][2] += qf1 * kf2; s[1][3] += qf1 * kf3;
            s[2][0] += qf2 * kf0; s[2][1] += qf2 * kf1; s[2][2] += qf2 * kf2; s[2][3] += qf2 * kf3;
            s[3][0] += qf3 * kf0; s[3][1] += qf3 * kf1; s[3][2] += qf3 * kf2; s[3][3] += qf3 * kf3;
        }

        // scale into exp2 domain, causal mask on diagonal tile
#pragma unroll
        for (int r = 0; r < 4; r++)
#pragma unroll
            for (int c = 0; c < 4; c++) s[r][c] *= scale2;
        if (j == qi) {
#pragma unroll
            for (int r = 0; r < 4; r++) {
                int grow = q0 + ty * 4 + r;
#pragma unroll
                for (int c = 0; c < 4; c++) {
                    int gcol = k0 + tx * 4 + c;
                    if (gcol > grow) s[r][c] = -1e30f;
                }
            }
        }

        // ---- online softmax (row reductions over 16 lanes) ----
#pragma unroll
        for (int r = 0; r < 4; r++) {
            float mm = fmaxf(fmaxf(s[r][0], s[r][1]), fmaxf(s[r][2], s[r][3]));
#pragma unroll
            for (int off = 8; off > 0; off >>= 1)
                mm = fmaxf(mm, __shfl_xor_sync(0xffffffffu, mm, off, 16));
            float mtot  = fmaxf(m_run[r], mm);
            float alpha = exp2f(m_run[r] - mtot);
            m_run[r] = mtot;
            float ls = 0.f;
#pragma unroll
            for (int c = 0; c < 4; c++) {
                s[r][c] = exp2f(s[r][c] - mtot);
                ls += s[r][c];
            }
#pragma unroll
            for (int off = 8; off > 0; off >>= 1)
                ls += __shfl_xor_sync(0xffffffffu, ls, off, 16);
            l_run[r] = l_run[r] * alpha + ls;
#pragma unroll
            for (int c = 0; c < 4; c++) o[r][c] *= alpha;
        }

        // ---- stage P in smem ----
#pragma unroll
        for (int r = 0; r < 4; r++) {
            float4 pv;
            pv.x = s[r][0]; pv.y = s[r][1]; pv.z = s[r][2]; pv.w = s[r][3];
            *(float4*)&sp[ty * 4 + r][tx * 4] = pv;
        }
        __syncthreads();

        // ---- O += P @ V ----
#pragma unroll 8
        for (int jj = 0; jj < 64; jj++) {
            float p0 = sp[ty * 4 + 0][jj];
            float p1 = sp[ty * 4 + 1][jj];
            float p2 = sp[ty * 4 + 2][jj];
            float p3 = sp[ty * 4 + 3][jj];
            float4 vf = *(float4*)&sv[jj][tx * 4];
            o[0][0] += p0 * vf.x; o[0][1] += p0 * vf.y; o[0][2] += p0 * vf.z; o[0][3] += p0 * vf.w;
            o[1][0] += p1 * vf.x; o[1][1] += p1 * vf.y; o[1][2] += p1 * vf.z; o[1][3] += p1 * vf.w;
            o[2][0] += p2 * vf.x; o[2][1] += p2 * vf.y; o[2][2] += p2 * vf.z; o[2][3] += p2 * vf.w;
            o[3][0] += p3 * vf.x; o[3][1] += p3 * vf.y; o[3][2] += p3 * vf.z; o[3][3] += p3 * vf.w;
        }
    }

    // ---- finalize: divide by l, write out ----
#pragma unroll
    for (int r = 0; r < 4; r++) {
        float inv = 1.f / l_run[r];
        size_t rowbase = ((size_t)b * SEQ + q0 + ty * 4 + r) * HDIM + tx * 4;
        float4 ov;
        ov.x = o[r][0] * inv; ov.y = o[r][1] * inv;
        ov.z = o[r][2] * inv; ov.w = o[r][3] * inv;
        *(float4*)&out[rowbase] = ov;
    }
}

// ---------------------------------------------------------------------------
extern "C" void kernel_launch(void* const* d_in, const int* in_sizes, int n_in,
                              void* d_out, int out_size)
{
    const float* x  = (const float*)d_in[0];
    const float* Wq = (const float*)d_in[1];
    const float* bq = (const float*)d_in[2];
    const float* Wk = (const float*)d_in[3];
    const float* bk = (const float*)d_in[4];
    const float* Wv = (const float*)d_in[5];
    const float* bv = (const float*)d_in[6];
    float* out = (float*)d_out;

    qkv_kernel<<<(BATCH * SEQ) / 64, 256>>>(x, Wq, bq, Wk, bk, Wv, bv);

    cudaFuncSetAttribute(attn_kernel, cudaFuncAttributeMaxDynamicSharedMemorySize, ATT_SMEM);
    dim3 grid(SEQ / 64, BATCH);
    attn_kernel<<<grid, 256, ATT_SMEM>>>(out);
}

// round 5
// speedup vs baseline: 2.3516x; 2.3516x over previous
#include <cuda_runtime.h>
#include <cstdint>
#include <math.h>

#define BATCH 16
#define SEQ   2048
#define DMODEL 1024
#define HDIM  64
#define NQKV  192

// scratch for fused q,k,v: [B*S][192]
__device__ float g_qkv[(size_t)BATCH * SEQ * NQKV];

__device__ __forceinline__ uint32_t f2tf(float x) {
    uint32_t r;
    asm("cvt.rna.tf32.f32 %0, %1;" : "=r"(r) : "f"(x));
    return r;
}

// D += A(16x8) * B(8x8), tf32 inputs, f32 accum
__device__ __forceinline__ void mma8(float* d, const uint32_t* a, uint32_t b0, uint32_t b1) {
    asm volatile(
        "mma.sync.aligned.m16n8k8.row.col.f32.tf32.tf32.f32 "
        "{%0,%1,%2,%3}, {%4,%5,%6,%7}, {%8,%9}, {%0,%1,%2,%3};\n"
        : "+f"(d[0]), "+f"(d[1]), "+f"(d[2]), "+f"(d[3])
        : "r"(a[0]), "r"(a[1]), "r"(a[2]), "r"(a[3]), "r"(b0), "r"(b1));
}

// ---------------------------------------------------------------------------
// Kernel 1: fused QKV projection with tf32 tensor cores.
// Block: 64 rows x 192 cols, 128 threads (4 warps, 2m x 2n grid of 32x96
// warp tiles). K-chunk 16 (two k8 mma steps). Operands stored in smem
// pre-converted to tf32.
// ---------------------------------------------------------------------------
#define SA_STR 20
#define SB_STR 200

__global__ __launch_bounds__(128, 3) void qkv_kernel(
    const float* __restrict__ x,
    const float* __restrict__ Wq, const float* __restrict__ bq,
    const float* __restrict__ Wk, const float* __restrict__ bk,
    const float* __restrict__ Wv, const float* __restrict__ bv)
{
    __shared__ uint32_t sA[64 * SA_STR];
    __shared__ uint32_t sB[16 * SB_STR];
    __shared__ float sbias[NQKV];

    const int tid  = threadIdx.x;
    const int w    = tid >> 5;
    const int lane = tid & 31;
    const int g    = lane >> 2;
    const int c    = lane & 3;
    const int wm   = w >> 1;      // 0..1  (32-row group)
    const int wn   = w & 1;       // 0..1  (96-col group)
    const int m0   = blockIdx.x * 64;

    for (int i = tid; i < NQKV; i += 128)
        sbias[i] = (i < 64) ? bq[i] : ((i < 128) ? bk[i - 64] : bv[i - 128]);

    float acc[2][12][4];
#pragma unroll
    for (int mi = 0; mi < 2; mi++)
#pragma unroll
        for (int ni = 0; ni < 12; ni++)
#pragma unroll
            for (int r = 0; r < 4; r++) acc[mi][ni][r] = 0.f;

    for (int kc = 0; kc < DMODEL / 16; kc++) {
        const int kb = kc * 16;
        // ---- A tile: 64x16 fp32 -> tf32 smem ----
#pragma unroll
        for (int i = 0; i < 2; i++) {
            int id = tid + i * 128;
            int row = id >> 2;
            int c4  = (id & 3) * 4;
            float4 v = *(const float4*)&x[(size_t)(m0 + row) * DMODEL + kb + c4];
            uint4 t = make_uint4(f2tf(v.x), f2tf(v.y), f2tf(v.z), f2tf(v.w));
            *(uint4*)&sA[row * SA_STR + c4] = t;
        }
        // ---- B tile: 16x192 (q|k|v) fp32 -> tf32 smem ----
#pragma unroll
        for (int i = 0; i < 6; i++) {
            int id  = tid + i * 128;
            int row = id / 48;
            int c4  = id % 48;
            int mm  = c4 >> 4;
            int lc  = (c4 & 15) * 4;
            const float* Wsrc = (mm == 0) ? Wq : ((mm == 1) ? Wk : Wv);
            float4 v = *(const float4*)&Wsrc[(size_t)(kb + row) * HDIM + lc];
            uint4 t = make_uint4(f2tf(v.x), f2tf(v.y), f2tf(v.z), f2tf(v.w));
            *(uint4*)&sB[row * SB_STR + c4 * 4] = t;
        }
        __syncthreads();

#pragma unroll
        for (int ks = 0; ks < 16; ks += 8) {
            uint32_t a[2][4];
#pragma unroll
            for (int mi = 0; mi < 2; mi++) {
                int r = 32 * wm + 16 * mi + g;
                a[mi][0] = sA[r * SA_STR + ks + c];
                a[mi][1] = sA[(r + 8) * SA_STR + ks + c];
                a[mi][2] = sA[r * SA_STR + ks + c + 4];
                a[mi][3] = sA[(r + 8) * SA_STR + ks + c + 4];
            }
#pragma unroll
            for (int ni = 0; ni < 12; ni++) {
                uint32_t b0 = sB[(ks + c) * SB_STR + 96 * wn + 8 * ni + g];
                uint32_t b1 = sB[(ks + c + 4) * SB_STR + 96 * wn + 8 * ni + g];
                mma8(acc[0][ni], a[0], b0, b1);
                mma8(acc[1][ni], a[1], b0, b1);
            }
        }
        __syncthreads();
    }

    // ---- epilogue: + bias, store fp32 ----
#pragma unroll
    for (int mi = 0; mi < 2; mi++) {
        int r = m0 + 32 * wm + 16 * mi + g;
#pragma unroll
        for (int ni = 0; ni < 12; ni++) {
            int col = 96 * wn + 8 * ni + 2 * c;
            float b0f = sbias[col], b1f = sbias[col + 1];
            float2 lo = make_float2(acc[mi][ni][0] + b0f, acc[mi][ni][1] + b1f);
            float2 hi = make_float2(acc[mi][ni][2] + b0f, acc[mi][ni][3] + b1f);
            *(float2*)&g_qkv[(size_t)r * NQKV + col] = lo;
            *(float2*)&g_qkv[(size_t)(r + 8) * NQKV + col] = hi;
        }
    }
}

// ---------------------------------------------------------------------------
// Kernel 2: causal flash attention with tf32 tensor cores.
// Block: 64 q-rows, 4 warps (16 q-rows each), kv tiles of 64.
// Q frags hoisted to registers (scale*log2e folded into tf32 convert).
// K kept row-major in smem (the .col B-frag layout reads K[j][d] directly,
// no transpose). K/V/P stored pre-converted to tf32.
// ---------------------------------------------------------------------------
#define SK_STR 68
#define SV_STR 72
#define SP_STR 68
#define ATT_SMEM ((64 * SK_STR + 64 * SV_STR + 64 * SP_STR) * 4)

__global__ __launch_bounds__(128, 3) void attn_kernel(float* __restrict__ out)
{
    extern __shared__ uint32_t dsm[];
    uint32_t* sk = dsm;                                   // [j][d] tf32
    uint32_t* sv = dsm + 64 * SK_STR;                     // [j][h] tf32
    uint32_t* sp = dsm + 64 * SK_STR + 64 * SV_STR;       // [q][j] tf32 (Q staging as f32)
    float* spf = (float*)sp;

    const int tid  = threadIdx.x;
    const int w    = tid >> 5;
    const int lane = tid & 31;
    const int g    = lane >> 2;
    const int c    = lane & 3;
    const int b    = blockIdx.y;
    const int qi   = (int)gridDim.x - 1 - (int)blockIdx.x;   // long blocks first
    const int q0   = qi * 64;
    const size_t base = (size_t)b * SEQ * NQKV;

    // fold 1/sqrt(64) and log2(e) into Q
    const float QS = 0.125f * 1.44269504088896340736f;

    // ---- stage Q tile, then hoist frags to registers ----
#pragma unroll
    for (int i = 0; i < 8; i++) {
        int id  = tid + i * 128;
        int row = id >> 4;
        int d4  = (id & 15) * 4;
        *(float4*)&spf[row * SP_STR + d4] =
            *(const float4*)&g_qkv[base + (size_t)(q0 + row) * NQKV + d4];
    }
    __syncthreads();

    uint32_t qa[8][4];
    {
        int r = 16 * w + g;
#pragma unroll
        for (int kd = 0; kd < 8; kd++) {
            qa[kd][0] = f2tf(spf[r * SP_STR + 8 * kd + c] * QS);
            qa[kd][1] = f2tf(spf[(r + 8) * SP_STR + 8 * kd + c] * QS);
            qa[kd][2] = f2tf(spf[r * SP_STR + 8 * kd + c + 4] * QS);
            qa[kd][3] = f2tf(spf[(r + 8) * SP_STR + 8 * kd + c + 4] * QS);
        }
    }

    float o[8][4];
#pragma unroll
    for (int ni = 0; ni < 8; ni++)
#pragma unroll
        for (int r = 0; r < 4; r++) o[ni][r] = 0.f;
    float m0r = -1e30f, m1r = -1e30f, l0r = 0.f, l1r = 0.f;

    for (int jt = 0; jt <= qi; jt++) {
        const int k0 = jt * 64;
        __syncthreads();   // all warps done with sp/sk/sv from previous phase

        // ---- load K,V tiles -> tf32 smem ----
#pragma unroll
        for (int i = 0; i < 8; i++) {
            int id  = tid + i * 128;
            int row = id >> 4;
            int d4  = (id & 15) * 4;
            const float* src = &g_qkv[base + (size_t)(k0 + row) * NQKV];
            float4 kq = *(const float4*)&src[64 + d4];
            *(uint4*)&sk[row * SK_STR + d4] =
                make_uint4(f2tf(kq.x), f2tf(kq.y), f2tf(kq.z), f2tf(kq.w));
            float4 vq = *(const float4*)&src[128 + d4];
            *(uint4*)&sv[row * SV_STR + d4] =
                make_uint4(f2tf(vq.x), f2tf(vq.y), f2tf(vq.z), f2tf(vq.w));
        }
        __syncthreads();

        // ---- S = Q K^T ----
        float s[8][4];
#pragma unroll
        for (int ni = 0; ni < 8; ni++)
#pragma unroll
            for (int r = 0; r < 4; r++) s[ni][r] = 0.f;

#pragma unroll
        for (int kd = 0; kd < 8; kd++) {
#pragma unroll
            for (int ni = 0; ni < 8; ni++) {
                uint32_t b0 = sk[(8 * ni + g) * SK_STR + 8 * kd + c];
                uint32_t b1 = sk[(8 * ni + g) * SK_STR + 8 * kd + c + 4];
                mma8(s[ni], qa[kd], b0, b1);
            }
        }

        // ---- causal mask (only the diagonal tile) ----
        if (jt == qi) {
            int rowg = q0 + 16 * w + g;
#pragma unroll
            for (int ni = 0; ni < 8; ni++) {
                int col = k0 + 8 * ni + 2 * c;
                if (col > rowg)         s[ni][0] = -1e30f;
                if (col + 1 > rowg)     s[ni][1] = -1e30f;
                if (col > rowg + 8)     s[ni][2] = -1e30f;
                if (col + 1 > rowg + 8) s[ni][3] = -1e30f;
            }
        }

        // ---- online softmax (rows g and g+8; quad-lane reduction) ----
        float lm0 = -1e30f, lm1 = -1e30f;
#pragma unroll
        for (int ni = 0; ni < 8; ni++) {
            lm0 = fmaxf(lm0, fmaxf(s[ni][0], s[ni][1]));
            lm1 = fmaxf(lm1, fmaxf(s[ni][2], s[ni][3]));
        }
        lm0 = fmaxf(lm0, __shfl_xor_sync(0xffffffffu, lm0, 1));
        lm0 = fmaxf(lm0, __shfl_xor_sync(0xffffffffu, lm0, 2));
        lm1 = fmaxf(lm1, __shfl_xor_sync(0xffffffffu, lm1, 1));
        lm1 = fmaxf(lm1, __shfl_xor_sync(0xffffffffu, lm1, 2));
        float mn0 = fmaxf(m0r, lm0), mn1 = fmaxf(m1r, lm1);
        float al0 = exp2f(m0r - mn0), al1 = exp2f(m1r - mn1);
        m0r = mn0; m1r = mn1;
        float ls0 = 0.f, ls1 = 0.f;
#pragma unroll
        for (int ni = 0; ni < 8; ni++) {
            s[ni][0] = exp2f(s[ni][0] - mn0); ls0 += s[ni][0];
            s[ni][1] = exp2f(s[ni][1] - mn0); ls0 += s[ni][1];
            s[ni][2] = exp2f(s[ni][2] - mn1); ls1 += s[ni][2];
            s[ni][3] = exp2f(s[ni][3] - mn1); ls1 += s[ni][3];
        }
        ls0 += __shfl_xor_sync(0xffffffffu, ls0, 1);
        ls0 += __shfl_xor_sync(0xffffffffu, ls0, 2);
        ls1 += __shfl_xor_sync(0xffffffffu, ls1, 1);
        ls1 += __shfl_xor_sync(0xffffffffu, ls1, 2);
        l0r = l0r * al0 + ls0;
        l1r = l1r * al1 + ls1;
#pragma unroll
        for (int ni = 0; ni < 8; ni++) {
            o[ni][0] *= al0; o[ni][1] *= al0;
            o[ni][2] *= al1; o[ni][3] *= al1;
        }

        // ---- stage P (tf32) in this warp's private sp rows ----
        {
            int r = 16 * w + g;
#pragma unroll
            for (int ni = 0; ni < 8; ni++) {
                int col = 8 * ni + 2 * c;
                *(uint2*)&sp[r * SP_STR + col] = make_uint2(f2tf(s[ni][0]), f2tf(s[ni][1]));
                *(uint2*)&sp[(r + 8) * SP_STR + col] = make_uint2(f2tf(s[ni][2]), f2tf(s[ni][3]));
            }
        }
        __syncwarp();

        // ---- O += P @ V ----
#pragma unroll
        for (int kd = 0; kd < 8; kd++) {
            uint32_t pa[4];
            int r = 16 * w + g;
            pa[0] = sp[r * SP_STR + 8 * kd + c];
            pa[1] = sp[(r + 8) * SP_STR + 8 * kd + c];
            pa[2] = sp[r * SP_STR + 8 * kd + c + 4];
            pa[3] = sp[(r + 8) * SP_STR + 8 * kd + c + 4];
#pragma unroll
            for (int ni = 0; ni < 8; ni++) {
                uint32_t b0 = sv[(8 * kd + c) * SV_STR + 8 * ni + g];
                uint32_t b1 = sv[(8 * kd + c + 4) * SV_STR + 8 * ni + g];
                mma8(o[ni], pa, b0, b1);
            }
        }
    }

    // ---- finalize ----
    float inv0 = 1.f / l0r, inv1 = 1.f / l1r;
    size_t orow = (size_t)b * SEQ + q0 + 16 * w + g;
#pragma unroll
    for (int ni = 0; ni < 8; ni++) {
        int col = 8 * ni + 2 * c;
        *(float2*)&out[orow * HDIM + col] =
            make_float2(o[ni][0] * inv0, o[ni][1] * inv0);
        *(float2*)&out[(orow + 8) * HDIM + col] =
            make_float2(o[ni][2] * inv1, o[ni][3] * inv1);
    }
}

// ---------------------------------------------------------------------------
extern "C" void kernel_launch(void* const* d_in, const int* in_sizes, int n_in,
                              void* d_out, int out_size)
{
    const float* x  = (const float*)d_in[0];
    const float* Wq = (const float*)d_in[1];
    const float* bq = (const float*)d_in[2];
    const float* Wk = (const float*)d_in[3];
    const float* bk = (const float*)d_in[4];
    const float* Wv = (const float*)d_in[5];
    const float* bv = (const float*)d_in[6];
    float* out = (float*)d_out;

    qkv_kernel<<<(BATCH * SEQ) / 64, 128>>>(x, Wq, bq, Wk, bk, Wv, bv);

    cudaFuncSetAttribute(attn_kernel, cudaFuncAttributeMaxDynamicSharedMemorySize, ATT_SMEM);
    dim3 grid(SEQ / 64, BATCH);
    attn_kernel<<<grid, 128, ATT_SMEM>>>(out);
}

// round 6
// speedup vs baseline: 2.9679x; 1.2621x over previous
#include <cuda_runtime.h>
#include <cstdint>
#include <math.h>

#define BATCH 16
#define SEQ   2048
#define DMODEL 1024
#define HDIM  64
#define NQKV  192

// scratch for fused q,k,v: [B*S][192]
__device__ float g_qkv[(size_t)BATCH * SEQ * NQKV];

__device__ __forceinline__ uint32_t f2tf(float x) {
    uint32_t r;
    asm("cvt.rna.tf32.f32 %0, %1;" : "=r"(r) : "f"(x));
    return r;
}
__device__ __forceinline__ uint4 cvt4(float4 v) {
    return make_uint4(f2tf(v.x), f2tf(v.y), f2tf(v.z), f2tf(v.w));
}

// D += A(16x8) * B(8x8), tf32 inputs, f32 accum
__device__ __forceinline__ void mma8(float* d, const uint32_t* a, uint32_t b0, uint32_t b1) {
    asm volatile(
        "mma.sync.aligned.m16n8k8.row.col.f32.tf32.tf32.f32 "
        "{%0,%1,%2,%3}, {%4,%5,%6,%7}, {%8,%9}, {%0,%1,%2,%3};\n"
        : "+f"(d[0]), "+f"(d[1]), "+f"(d[2]), "+f"(d[3])
        : "r"(a[0]), "r"(a[1]), "r"(a[2]), "r"(a[3]), "r"(b0), "r"(b1));
}

// ---------------------------------------------------------------------------
// Kernel 1: fused QKV projection, tf32 tensor cores.
// Block tile 128x192, 256 threads (8 warps: 4m x 2n grid of 32x96 warp tiles),
// BK=16, register-prefetch double buffering of global loads.
// ---------------------------------------------------------------------------
#define SA_STR 20
#define SB_STR 200

__global__ __launch_bounds__(256, 1) void qkv_kernel(
    const float* __restrict__ x,
    const float* __restrict__ Wq, const float* __restrict__ bq,
    const float* __restrict__ Wk, const float* __restrict__ bk,
    const float* __restrict__ Wv, const float* __restrict__ bv)
{
    __shared__ uint32_t sA[128 * SA_STR];
    __shared__ uint32_t sB[16 * SB_STR];
    __shared__ float sbias[NQKV];

    const int tid  = threadIdx.x;
    const int w    = tid >> 5;
    const int lane = tid & 31;
    const int g    = lane >> 2;
    const int c    = lane & 3;
    const int wm   = w >> 1;      // 0..3 (32-row group)
    const int wn   = w & 1;       // 0..1 (96-col group)
    const int m0   = blockIdx.x * 128;

    for (int i = tid; i < NQKV; i += 256)
        sbias[i] = (i < 64) ? bq[i] : ((i < 128) ? bk[i - 64] : bv[i - 128]);

    // ---- per-thread load slots (constant across chunks except kb) ----
    // A tile: 128x16 = 512 float4, 2 per thread
    int a_row[2], a_c4[2];
#pragma unroll
    for (int i = 0; i < 2; i++) {
        int id = tid + i * 256;
        a_row[i] = id >> 2;
        a_c4[i]  = (id & 3) * 4;
    }
    // B tile: 16x192 = 768 float4, 3 per thread
    int b_row[3], b_c4[3];
    const float* b_src[3];
#pragma unroll
    for (int i = 0; i < 3; i++) {
        int id = tid + i * 256;
        b_row[i] = id / 48;
        b_c4[i]  = id % 48;
        int mm = b_c4[i] >> 4;
        int lc = (b_c4[i] & 15) * 4;
        const float* Wsrc = (mm == 0) ? Wq : ((mm == 1) ? Wk : Wv);
        b_src[i] = Wsrc + (size_t)b_row[i] * HDIM + lc;
    }

    float acc[2][12][4];
#pragma unroll
    for (int mi = 0; mi < 2; mi++)
#pragma unroll
        for (int ni = 0; ni < 12; ni++)
#pragma unroll
            for (int r = 0; r < 4; r++) acc[mi][ni][r] = 0.f;

    float4 pa[2], pb[3];
    // prefetch chunk 0
#pragma unroll
    for (int i = 0; i < 2; i++)
        pa[i] = *(const float4*)&x[(size_t)(m0 + a_row[i]) * DMODEL + a_c4[i]];
#pragma unroll
    for (int i = 0; i < 3; i++)
        pb[i] = *(const float4*)(b_src[i]);

    for (int kc = 0; kc < DMODEL / 16; kc++) {
        // ---- commit prefetched chunk to smem (tf32) ----
#pragma unroll
        for (int i = 0; i < 2; i++)
            *(uint4*)&sA[a_row[i] * SA_STR + a_c4[i]] = cvt4(pa[i]);
#pragma unroll
        for (int i = 0; i < 3; i++)
            *(uint4*)&sB[b_row[i] * SB_STR + b_c4[i] * 4] = cvt4(pb[i]);

        // ---- issue next chunk's global loads (overlap with compute) ----
        if (kc + 1 < DMODEL / 16) {
            int kb = (kc + 1) * 16;
#pragma unroll
            for (int i = 0; i < 2; i++)
                pa[i] = *(const float4*)&x[(size_t)(m0 + a_row[i]) * DMODEL + kb + a_c4[i]];
#pragma unroll
            for (int i = 0; i < 3; i++)
                pb[i] = *(const float4*)(b_src[i] + (size_t)kb * HDIM);
        }
        __syncthreads();

#pragma unroll
        for (int ks = 0; ks < 16; ks += 8) {
            uint32_t a[2][4];
#pragma unroll
            for (int mi = 0; mi < 2; mi++) {
                int r = 32 * wm + 16 * mi + g;
                a[mi][0] = sA[r * SA_STR + ks + c];
                a[mi][1] = sA[(r + 8) * SA_STR + ks + c];
                a[mi][2] = sA[r * SA_STR + ks + c + 4];
                a[mi][3] = sA[(r + 8) * SA_STR + ks + c + 4];
            }
#pragma unroll
            for (int ni = 0; ni < 12; ni++) {
                uint32_t b0 = sB[(ks + c) * SB_STR + 96 * wn + 8 * ni + g];
                uint32_t b1 = sB[(ks + c + 4) * SB_STR + 96 * wn + 8 * ni + g];
                mma8(acc[0][ni], a[0], b0, b1);
                mma8(acc[1][ni], a[1], b0, b1);
            }
        }
        __syncthreads();
    }

    // ---- epilogue: + bias, store fp32 ----
#pragma unroll
    for (int mi = 0; mi < 2; mi++) {
        int r = m0 + 32 * wm + 16 * mi + g;
#pragma unroll
        for (int ni = 0; ni < 12; ni++) {
            int col = 96 * wn + 8 * ni + 2 * c;
            float b0f = sbias[col], b1f = sbias[col + 1];
            float2 lo = make_float2(acc[mi][ni][0] + b0f, acc[mi][ni][1] + b1f);
            float2 hi = make_float2(acc[mi][ni][2] + b0f, acc[mi][ni][3] + b1f);
            *(float2*)&g_qkv[(size_t)r * NQKV + col] = lo;
            *(float2*)&g_qkv[(size_t)(r + 8) * NQKV + col] = hi;
        }
    }
}

// ---------------------------------------------------------------------------
// Kernel 2: causal flash attention, tf32 tensor cores.
// Block: 128 q-rows, 256 threads (8 warps x 16 q-rows), kv tiles of 64.
// K/V register-prefetched (LDG overlaps compute), warps fully above the
// kv tile skip compute. Q frags in registers (scale*log2e folded in).
// ---------------------------------------------------------------------------
#define SK_STR 68
#define SV_STR 72
#define SP_STR 68
#define ATT_SMEM ((64 * SK_STR + 64 * SV_STR + 128 * SP_STR) * 4)

__global__ __launch_bounds__(256, 1) void attn_kernel(float* __restrict__ out)
{
    extern __shared__ uint32_t dsm[];
    uint32_t* sk = dsm;                                   // [j][d] tf32
    uint32_t* sv = dsm + 64 * SK_STR;                     // [j][h] tf32
    uint32_t* sp = dsm + 64 * SK_STR + 64 * SV_STR;       // [q 0..127][j] tf32 (Q staging f32)
    float* spf = (float*)sp;

    const int tid  = threadIdx.x;
    const int w    = tid >> 5;
    const int lane = tid & 31;
    const int g    = lane >> 2;
    const int c    = lane & 3;
    const int b    = blockIdx.y;
    const int qi   = (int)gridDim.x - 1 - (int)blockIdx.x;   // long blocks first
    const int q0   = qi * 128;
    const int jmax = 2 * qi + 1;
    const size_t base = (size_t)b * SEQ * NQKV;

    const float QS = 0.125f * 1.44269504088896340736f;   // 1/sqrt(64) * log2(e)

    // ---- stage Q tile (128x64 f32) ----
#pragma unroll
    for (int i = 0; i < 8; i++) {
        int id  = tid + i * 256;
        int row = id >> 4;
        int d4  = (id & 15) * 4;
        *(float4*)&spf[row * SP_STR + d4] =
            *(const float4*)&g_qkv[base + (size_t)(q0 + row) * NQKV + d4];
    }
    __syncthreads();

    // ---- hoist Q frags to registers ----
    uint32_t qa[8][4];
    {
        int r = 16 * w + g;
#pragma unroll
        for (int kd = 0; kd < 8; kd++) {
            qa[kd][0] = f2tf(spf[r * SP_STR + 8 * kd + c] * QS);
            qa[kd][1] = f2tf(spf[(r + 8) * SP_STR + 8 * kd + c] * QS);
            qa[kd][2] = f2tf(spf[r * SP_STR + 8 * kd + c + 4] * QS);
            qa[kd][3] = f2tf(spf[(r + 8) * SP_STR + 8 * kd + c + 4] * QS);
        }
    }

    float o[8][4];
#pragma unroll
    for (int ni = 0; ni < 8; ni++)
#pragma unroll
        for (int r = 0; r < 4; r++) o[ni][r] = 0.f;
    float m0r = -1e30f, m1r = -1e30f, l0r = 0.f, l1r = 0.f;

    // per-thread K/V load slots: 64 rows x 16 float4 per matrix, 4 per thread
    int kv_row[4], kv_d4[4];
#pragma unroll
    for (int i = 0; i < 4; i++) {
        int id = tid + i * 256;
        kv_row[i] = id >> 4;
        kv_d4[i]  = (id & 15) * 4;
    }

    // prefetch tile 0
    float4 pk[4], pv[4];
#pragma unroll
    for (int i = 0; i < 4; i++) {
        const float* src = &g_qkv[base + (size_t)kv_row[i] * NQKV];
        pk[i] = *(const float4*)&src[64 + kv_d4[i]];
        pv[i] = *(const float4*)&src[128 + kv_d4[i]];
    }

    for (int jt = 0; jt <= jmax; jt++) {
        const int k0 = jt * 64;
        __syncthreads();   // prior compute (and Q hoist) done — smem free

        // ---- commit prefetched K/V to smem (tf32) ----
#pragma unroll
        for (int i = 0; i < 4; i++) {
            *(uint4*)&sk[kv_row[i] * SK_STR + kv_d4[i]] = cvt4(pk[i]);
            *(uint4*)&sv[kv_row[i] * SV_STR + kv_d4[i]] = cvt4(pv[i]);
        }
        // ---- issue next tile's global loads ----
        if (jt < jmax) {
            int kn = (jt + 1) * 64;
#pragma unroll
            for (int i = 0; i < 4; i++) {
                const float* src = &g_qkv[base + (size_t)(kn + kv_row[i]) * NQKV];
                pk[i] = *(const float4*)&src[64 + kv_d4[i]];
                pv[i] = *(const float4*)&src[128 + kv_d4[i]];
            }
        }
        __syncthreads();

        // warps whose rows are entirely above this kv tile: nothing to do
        if (k0 > q0 + 16 * w + 15) continue;

        // ---- S = Q K^T ----
        float s[8][4];
#pragma unroll
        for (int ni = 0; ni < 8; ni++)
#pragma unroll
            for (int r = 0; r < 4; r++) s[ni][r] = 0.f;

#pragma unroll
        for (int kd = 0; kd < 8; kd++) {
#pragma unroll
            for (int ni = 0; ni < 8; ni++) {
                uint32_t b0 = sk[(8 * ni + g) * SK_STR + 8 * kd + c];
                uint32_t b1 = sk[(8 * ni + g) * SK_STR + 8 * kd + c + 4];
                mma8(s[ni], qa[kd], b0, b1);
            }
        }

        // ---- causal mask (any tile intersecting the boundary) ----
        if (k0 + 63 > q0 + 16 * w) {
            int rowg = q0 + 16 * w + g;
#pragma unroll
            for (int ni = 0; ni < 8; ni++) {
                int col = k0 + 8 * ni + 2 * c;
                if (col > rowg)         s[ni][0] = -1e30f;
                if (col + 1 > rowg)     s[ni][1] = -1e30f;
                if (col > rowg + 8)     s[ni][2] = -1e30f;
                if (col + 1 > rowg + 8) s[ni][3] = -1e30f;
            }
        }

        // ---- online softmax (rows g and g+8; quad-lane reduction) ----
        float lm0 = -1e30f, lm1 = -1e30f;
#pragma unroll
        for (int ni = 0; ni < 8; ni++) {
            lm0 = fmaxf(lm0, fmaxf(s[ni][0], s[ni][1]));
            lm1 = fmaxf(lm1, fmaxf(s[ni][2], s[ni][3]));
        }
        lm0 = fmaxf(lm0, __shfl_xor_sync(0xffffffffu, lm0, 1));
        lm0 = fmaxf(lm0, __shfl_xor_sync(0xffffffffu, lm0, 2));
        lm1 = fmaxf(lm1, __shfl_xor_sync(0xffffffffu, lm1, 1));
        lm1 = fmaxf(lm1, __shfl_xor_sync(0xffffffffu, lm1, 2));
        float mn0 = fmaxf(m0r, lm0), mn1 = fmaxf(m1r, lm1);
        float al0 = exp2f(m0r - mn0), al1 = exp2f(m1r - mn1);
        m0r = mn0; m1r = mn1;
        float ls0 = 0.f, ls1 = 0.f;
#pragma unroll
        for (int ni = 0; ni < 8; ni++) {
            s[ni][0] = exp2f(s[ni][0] - mn0); ls0 += s[ni][0];
            s[ni][1] = exp2f(s[ni][1] - mn0); ls0 += s[ni][1];
            s[ni][2] = exp2f(s[ni][2] - mn1); ls1 += s[ni][2];
            s[ni][3] = exp2f(s[ni][3] - mn1); ls1 += s[ni][3];
        }
        ls0 += __shfl_xor_sync(0xffffffffu, ls0, 1);
        ls0 += __shfl_xor_sync(0xffffffffu, ls0, 2);
        ls1 += __shfl_xor_sync(0xffffffffu, ls1, 1);
        ls1 += __shfl_xor_sync(0xffffffffu, ls1, 2);
        l0r = l0r * al0 + ls0;
        l1r = l1r * al1 + ls1;
#pragma unroll
        for (int ni = 0; ni < 8; ni++) {
            o[ni][0] *= al0; o[ni][1] *= al0;
            o[ni][2] *= al1; o[ni][3] *= al1;
        }

        // ---- stage P (tf32) in this warp's private sp rows ----
        {
            int r = 16 * w + g;
#pragma unroll
            for (int ni = 0; ni < 8; ni++) {
                int col = 8 * ni + 2 * c;
                *(uint2*)&sp[r * SP_STR + col] = make_uint2(f2tf(s[ni][0]), f2tf(s[ni][1]));
                *(uint2*)&sp[(r + 8) * SP_STR + col] = make_uint2(f2tf(s[ni][2]), f2tf(s[ni][3]));
            }
        }
        __syncwarp();

        // ---- O += P @ V ----
#pragma unroll
        for (int kd = 0; kd < 8; kd++) {
            uint32_t pa[4];
            int r = 16 * w + g;
            pa[0] = sp[r * SP_STR + 8 * kd + c];
            pa[1] = sp[(r + 8) * SP_STR + 8 * kd + c];
            pa[2] = sp[r * SP_STR + 8 * kd + c + 4];
            pa[3] = sp[(r + 8) * SP_STR + 8 * kd + c + 4];
#pragma unroll
            for (int ni = 0; ni < 8; ni++) {
                uint32_t b0 = sv[(8 * kd + c) * SV_STR + 8 * ni + g];
                uint32_t b1 = sv[(8 * kd + c + 4) * SV_STR + 8 * ni + g];
                mma8(o[ni], pa, b0, b1);
            }
        }
    }

    // ---- finalize ----
    float inv0 = 1.f / l0r, inv1 = 1.f / l1r;
    size_t orow = (size_t)b * SEQ + q0 + 16 * w + g;
#pragma unroll
    for (int ni = 0; ni < 8; ni++) {
        int col = 8 * ni + 2 * c;
        *(float2*)&out[orow * HDIM + col] =
            make_float2(o[ni][0] * inv0, o[ni][1] * inv0);
        *(float2*)&out[(orow + 8) * HDIM + col] =
            make_float2(o[ni][2] * inv1, o[ni][3] * inv1);
    }
}

// ---------------------------------------------------------------------------
extern "C" void kernel_launch(void* const* d_in, const int* in_sizes, int n_in,
                              void* d_out, int out_size)
{
    const float* x  = (const float*)d_in[0];
    const float* Wq = (const float*)d_in[1];
    const float* bq = (const float*)d_in[2];
    const float* Wk = (const float*)d_in[3];
    const float* bk = (const float*)d_in[4];
    const float* Wv = (const float*)d_in[5];
    const float* bv = (const float*)d_in[6];
    float* out = (float*)d_out;

    qkv_kernel<<<(BATCH * SEQ) / 128, 256>>>(x, Wq, bq, Wk, bk, Wv, bv);

    cudaFuncSetAttribute(attn_kernel, cudaFuncAttributeMaxDynamicSharedMemorySize, ATT_SMEM);
    dim3 grid(SEQ / 128, BATCH);
    attn_kernel<<<grid, 256, ATT_SMEM>>>(out);
}

// round 7
// speedup vs baseline: 3.4233x; 1.1534x over previous
#include <cuda_runtime.h>
#include <cstdint>
#include <math.h>

#define BATCH 16
#define SEQ   2048
#define DMODEL 1024
#define HDIM  64
#define NQKV  192

// scratch: q (pre-scaled, tf32 bits) | k (tf32 bits) | v (tf32 bits), [B*S][192]
__device__ float g_qkv[(size_t)BATCH * SEQ * NQKV];

__device__ __forceinline__ uint32_t f2tf(float x) {
    uint32_t r;
    asm("cvt.rna.tf32.f32 %0, %1;" : "=r"(r) : "f"(x));
    return r;
}
__device__ __forceinline__ float ex2(float x) {
    float r;
    asm("ex2.approx.ftz.f32 %0, %1;" : "=f"(r) : "f"(x));
    return r;
}
__device__ __forceinline__ void cp16(uint32_t dst, const void* src) {
    asm volatile("cp.async.cg.shared.global [%0], [%1], 16;" :: "r"(dst), "l"(src));
}

// D += A(16x8) * B(8x8), tf32 inputs, f32 accum
__device__ __forceinline__ void mma8(float* d, const uint32_t* a, uint32_t b0, uint32_t b1) {
    asm volatile(
        "mma.sync.aligned.m16n8k8.row.col.f32.tf32.tf32.f32 "
        "{%0,%1,%2,%3}, {%4,%5,%6,%7}, {%8,%9}, {%0,%1,%2,%3};\n"
        : "+f"(d[0]), "+f"(d[1]), "+f"(d[2]), "+f"(d[3])
        : "r"(a[0]), "r"(a[1]), "r"(a[2]), "r"(a[3]), "r"(b0), "r"(b1));
}

#define QSCALE (0.125f * 1.44269504088896340736f)   // 1/sqrt(64) * log2(e)

// ---------------------------------------------------------------------------
// Kernel 1: fused QKV projection, tf32 tensor cores.
// Block tile 128x192, 512 threads (16 warps: 4m x 4n, warp tile 32x48,
// mi=2 ni=6, 48 acc regs). Register-prefetch double buffering.
// Epilogue writes q pre-scaled + tf32, k/v tf32 (bit patterns in float).
// ---------------------------------------------------------------------------
#define SA_STR 20
#define SB_STR 200

__global__ __launch_bounds__(512, 1) void qkv_kernel(
    const float* __restrict__ x,
    const float* __restrict__ Wq, const float* __restrict__ bq,
    const float* __restrict__ Wk, const float* __restrict__ bk,
    const float* __restrict__ Wv, const float* __restrict__ bv)
{
    __shared__ uint32_t sA[128 * SA_STR];
    __shared__ uint32_t sB[16 * SB_STR];
    __shared__ float sbias[NQKV];

    const int tid  = threadIdx.x;
    const int w    = tid >> 5;
    const int lane = tid & 31;
    const int g    = lane >> 2;
    const int c    = lane & 3;
    const int wm   = w >> 2;      // 0..3 (32-row group)
    const int wn   = w & 3;       // 0..3 (48-col group)
    const int m0   = blockIdx.x * 128;

    if (tid < NQKV)
        sbias[tid] = (tid < 64) ? bq[tid] : ((tid < 128) ? bk[tid - 64] : bv[tid - 128]);

    // ---- per-thread load slots ----
    // A tile: 128x16 = 512 float4 -> 1 per thread
    const int a_row = tid >> 2;
    const int a_c4  = (tid & 3) * 4;
    // B tile: 16x192 = 768 float4 -> slot0 all threads, slot1 for tid<256
    int b_row[2], b_c4[2];
    const float* b_src[2];
#pragma unroll
    for (int i = 0; i < 2; i++) {
        int id = tid + i * 512;
        b_row[i] = id / 48;
        b_c4[i]  = id % 48;
        int mm = b_c4[i] >> 4;
        int lc = (b_c4[i] & 15) * 4;
        const float* Wsrc = (mm == 0) ? Wq : ((mm == 1) ? Wk : Wv);
        b_src[i] = Wsrc + (size_t)(b_row[i] & 15) * HDIM + lc;
    }
    const bool b2ok = (tid < 256);

    float acc[2][6][4];
#pragma unroll
    for (int mi = 0; mi < 2; mi++)
#pragma unroll
        for (int ni = 0; ni < 6; ni++)
#pragma unroll
            for (int r = 0; r < 4; r++) acc[mi][ni][r] = 0.f;

    float4 pa, pb0, pb1;
    pa  = *(const float4*)&x[(size_t)(m0 + a_row) * DMODEL + a_c4];
    pb0 = *(const float4*)(b_src[0]);
    if (b2ok) pb1 = *(const float4*)(b_src[1]);

    for (int kc = 0; kc < DMODEL / 16; kc++) {
        // ---- commit prefetched chunk to smem (tf32) ----
        *(uint4*)&sA[a_row * SA_STR + a_c4] =
            make_uint4(f2tf(pa.x), f2tf(pa.y), f2tf(pa.z), f2tf(pa.w));
        *(uint4*)&sB[(b_row[0] & 15) * SB_STR + b_c4[0] * 4] =
            make_uint4(f2tf(pb0.x), f2tf(pb0.y), f2tf(pb0.z), f2tf(pb0.w));
        if (b2ok)
            *(uint4*)&sB[(b_row[1] & 15) * SB_STR + b_c4[1] * 4] =
                make_uint4(f2tf(pb1.x), f2tf(pb1.y), f2tf(pb1.z), f2tf(pb1.w));

        // ---- issue next chunk's global loads ----
        if (kc + 1 < DMODEL / 16) {
            int kb = (kc + 1) * 16;
            pa  = *(const float4*)&x[(size_t)(m0 + a_row) * DMODEL + kb + a_c4];
            pb0 = *(const float4*)(b_src[0] + (size_t)kb * HDIM);
            if (b2ok) pb1 = *(const float4*)(b_src[1] + (size_t)kb * HDIM);
        }
        __syncthreads();

#pragma unroll
        for (int ks = 0; ks < 16; ks += 8) {
            uint32_t a[2][4];
#pragma unroll
            for (int mi = 0; mi < 2; mi++) {
                int r = 32 * wm + 16 * mi + g;
                a[mi][0] = sA[r * SA_STR + ks + c];
                a[mi][1] = sA[(r + 8) * SA_STR + ks + c];
                a[mi][2] = sA[r * SA_STR + ks + c + 4];
                a[mi][3] = sA[(r + 8) * SA_STR + ks + c + 4];
            }
#pragma unroll
            for (int ni = 0; ni < 6; ni++) {
                uint32_t b0 = sB[(ks + c) * SB_STR + 48 * wn + 8 * ni + g];
                uint32_t b1 = sB[(ks + c + 4) * SB_STR + 48 * wn + 8 * ni + g];
                mma8(acc[0][ni], a[0], b0, b1);
                mma8(acc[1][ni], a[1], b0, b1);
            }
        }
        __syncthreads();
    }

    // ---- epilogue: +bias, q*=QSCALE, convert to tf32 bits, store ----
#pragma unroll
    for (int mi = 0; mi < 2; mi++) {
        int r = m0 + 32 * wm + 16 * mi + g;
#pragma unroll
        for (int ni = 0; ni < 6; ni++) {
            int col = 48 * wn + 8 * ni + 2 * c;
            float b0f = sbias[col], b1f = sbias[col + 1];
            float sc = (col < 64) ? QSCALE : 1.0f;
            float lo0 = (acc[mi][ni][0] + b0f) * sc;
            float lo1 = (acc[mi][ni][1] + b1f) * sc;
            float hi0 = (acc[mi][ni][2] + b0f) * sc;
            float hi1 = (acc[mi][ni][3] + b1f) * sc;
            *(float2*)&g_qkv[(size_t)r * NQKV + col] =
                make_float2(__uint_as_float(f2tf(lo0)), __uint_as_float(f2tf(lo1)));
            *(float2*)&g_qkv[(size_t)(r + 8) * NQKV + col] =
                make_float2(__uint_as_float(f2tf(hi0)), __uint_as_float(f2tf(hi1)));
        }
    }
}

// ---------------------------------------------------------------------------
// Kernel 2: causal flash attention, tf32 tensor cores.
// Block: 64 q-rows, 128 threads (4 warps x 16 q-rows), kv tiles of 64.
// K/V arrive via cp.async 2-stage double buffer (already tf32 in g_qkv).
// P passes warp-register shuffle (no smem) -> smem = K/V only -> 3 CTAs/SM.
// ---------------------------------------------------------------------------
#define SK_STR 68
#define SV_STR 72
#define STAGE_U32 (64 * SK_STR + 64 * SV_STR)      // 8960 u32 per stage
#define ATT_SMEM (2 * STAGE_U32 * 4)               // 71680 B

__global__ __launch_bounds__(128, 3) void attn_kernel(float* __restrict__ out)
{
    extern __shared__ uint32_t dsm[];
    const uint32_t smem_u32 = (uint32_t)__cvta_generic_to_shared(dsm);

    const int tid  = threadIdx.x;
    const int lane = tid & 31;
    const int w    = tid >> 5;
    const int g    = lane >> 2;
    const int c    = lane & 3;
    const int b    = blockIdx.y;
    const int qi   = (int)gridDim.x - 1 - (int)blockIdx.x;   // long blocks first
    const int q0   = qi * 64;
    const size_t base = (size_t)b * SEQ * NQKV;

    // per-thread cp.async slots: 1024 x 16B per matrix, 8 per thread
    const int cp_row = tid >> 1;                 // wrong granularity? no: see below
    // id = tid + i*128; row = id>>4 (0..63), chunk = id&15
    (void)cp_row;

    // ---- issue tile 0 prefetch ----
    {
        const int k0 = 0;
#pragma unroll
        for (int i = 0; i < 8; i++) {
            int id  = tid + i * 128;
            int row = id >> 4;
            int ch  = id & 15;
            const float* src = &g_qkv[base + (size_t)(k0 + row) * NQKV];
            cp16(smem_u32 + (row * SK_STR + ch * 4) * 4, src + 64 + ch * 4);
            cp16(smem_u32 + (64 * SK_STR + row * SV_STR + ch * 4) * 4, src + 128 + ch * 4);
        }
        asm volatile("cp.async.commit_group;" ::: "memory");
    }

    // ---- hoist Q frags directly from gmem (tf32 bits, pre-scaled) ----
    uint32_t qa[8][4];
    {
        const float* q0p = &g_qkv[base + (size_t)(q0 + 16 * w + g) * NQKV];
        const float* q1p = q0p + 8 * NQKV;
#pragma unroll
        for (int kd = 0; kd < 8; kd++) {
            qa[kd][0] = __float_as_uint(q0p[8 * kd + c]);
            qa[kd][1] = __float_as_uint(q1p[8 * kd + c]);
            qa[kd][2] = __float_as_uint(q0p[8 * kd + c + 4]);
            qa[kd][3] = __float_as_uint(q1p[8 * kd + c + 4]);
        }
    }

    float o[8][4];
#pragma unroll
    for (int ni = 0; ni < 8; ni++)
#pragma unroll
        for (int r = 0; r < 4; r++) o[ni][r] = 0.f;
    float m0r = -1e30f, m1r = -1e30f, l0r = 0.f, l1r = 0.f;

    for (int jt = 0; jt <= qi; jt++) {
        // ---- issue next tile into the other stage ----
        if (jt < qi) {
            int kn = (jt + 1) * 64;
            uint32_t sb = smem_u32 + ((jt + 1) & 1) * STAGE_U32 * 4;
#pragma unroll
            for (int i = 0; i < 8; i++) {
                int id  = tid + i * 128;
                int row = id >> 4;
                int ch  = id & 15;
                const float* src = &g_qkv[base + (size_t)(kn + row) * NQKV];
                cp16(sb + (row * SK_STR + ch * 4) * 4, src + 64 + ch * 4);
                cp16(sb + (64 * SK_STR + row * SV_STR + ch * 4) * 4, src + 128 + ch * 4);
            }
            asm volatile("cp.async.commit_group;" ::: "memory");
            asm volatile("cp.async.wait_group 1;" ::: "memory");
        } else {
            asm volatile("cp.async.wait_group 0;" ::: "memory");
        }
        __syncthreads();   // tile jt visible to all

        const uint32_t* sk = dsm + (jt & 1) * STAGE_U32;
        const uint32_t* sv = sk + 64 * SK_STR;

        // ---- S = Q K^T ----
        float s[8][4];
#pragma unroll
        for (int ni = 0; ni < 8; ni++)
#pragma unroll
            for (int r = 0; r < 4; r++) s[ni][r] = 0.f;

#pragma unroll
        for (int kd = 0; kd < 8; kd++) {
#pragma unroll
            for (int ni = 0; ni < 8; ni++) {
                uint32_t b0 = sk[(8 * ni + g) * SK_STR + 8 * kd + c];
                uint32_t b1 = sk[(8 * ni + g) * SK_STR + 8 * kd + c + 4];
                mma8(s[ni], qa[kd], b0, b1);
            }
        }

        // ---- causal mask on diagonal tile ----
        if (jt == qi) {
            int rowg = q0 + 16 * w + g;
            int k0c  = jt * 64;
#pragma unroll
            for (int ni = 0; ni < 8; ni++) {
                int col = k0c + 8 * ni + 2 * c;
                if (col > rowg)         s[ni][0] = -1e30f;
                if (col + 1 > rowg)     s[ni][1] = -1e30f;
                if (col > rowg + 8)     s[ni][2] = -1e30f;
                if (col + 1 > rowg + 8) s[ni][3] = -1e30f;
            }
        }

        // ---- online softmax (log2 domain; quad-lane reductions) ----
        float lm0 = -1e30f, lm1 = -1e30f;
#pragma unroll
        for (int ni = 0; ni < 8; ni++) {
            lm0 = fmaxf(lm0, fmaxf(s[ni][0], s[ni][1]));
            lm1 = fmaxf(lm1, fmaxf(s[ni][2], s[ni][3]));
        }
        lm0 = fmaxf(lm0, __shfl_xor_sync(0xffffffffu, lm0, 1));
        lm0 = fmaxf(lm0, __shfl_xor_sync(0xffffffffu, lm0, 2));
        lm1 = fmaxf(lm1, __shfl_xor_sync(0xffffffffu, lm1, 1));
        lm1 = fmaxf(lm1, __shfl_xor_sync(0xffffffffu, lm1, 2));
        float mn0 = fmaxf(m0r, lm0), mn1 = fmaxf(m1r, lm1);
        float al0 = ex2(m0r - mn0), al1 = ex2(m1r - mn1);
        m0r = mn0; m1r = mn1;
        float ls0 = 0.f, ls1 = 0.f;
#pragma unroll
        for (int ni = 0; ni < 8; ni++) {
            s[ni][0] = ex2(s[ni][0] - mn0); ls0 += s[ni][0];
            s[ni][1] = ex2(s[ni][1] - mn0); ls0 += s[ni][1];
            s[ni][2] = ex2(s[ni][2] - mn1); ls1 += s[ni][2];
            s[ni][3] = ex2(s[ni][3] - mn1); ls1 += s[ni][3];
        }
        ls0 += __shfl_xor_sync(0xffffffffu, ls0, 1);
        ls0 += __shfl_xor_sync(0xffffffffu, ls0, 2);
        ls1 += __shfl_xor_sync(0xffffffffu, ls1, 1);
        ls1 += __shfl_xor_sync(0xffffffffu, ls1, 2);
        l0r = l0r * al0 + ls0;
        l1r = l1r * al1 + ls1;
#pragma unroll
        for (int ni = 0; ni < 8; ni++) {
            o[ni][0] *= al0; o[ni][1] *= al0;
            o[ni][2] *= al1; o[ni][3] *= al1;
        }

        // ---- convert P to tf32 ----
        uint32_t ps[8][4];
#pragma unroll
        for (int ni = 0; ni < 8; ni++) {
            ps[ni][0] = f2tf(s[ni][0]);
            ps[ni][1] = f2tf(s[ni][1]);
            ps[ni][2] = f2tf(s[ni][2]);
            ps[ni][3] = f2tf(s[ni][3]);
        }

        // ---- O += P @ V  (P C-frag -> A-frag via shuffles, no smem) ----
        const int srcA = (lane & 28) | (c >> 1);
        const int srcB = srcA + 2;
        const bool odd = (c & 1);
#pragma unroll
        for (int kd = 0; kd < 8; kd++) {
            uint32_t pa[4], x0, y0;
            x0 = __shfl_sync(0xffffffffu, ps[kd][0], srcA);
            y0 = __shfl_sync(0xffffffffu, ps[kd][1], srcA);
            pa[0] = odd ? y0 : x0;
            x0 = __shfl_sync(0xffffffffu, ps[kd][2], srcA);
            y0 = __shfl_sync(0xffffffffu, ps[kd][3], srcA);
            pa[1] = odd ? y0 : x0;
            x0 = __shfl_sync(0xffffffffu, ps[kd][0], srcB);
            y0 = __shfl_sync(0xffffffffu, ps[kd][1], srcB);
            pa[2] = odd ? y0 : x0;
            x0 = __shfl_sync(0xffffffffu, ps[kd][2], srcB);
            y0 = __shfl_sync(0xffffffffu, ps[kd][3], srcB);
            pa[3] = odd ? y0 : x0;
#pragma unroll
            for (int ni = 0; ni < 8; ni++) {
                uint32_t b0 = sv[(8 * kd + c) * SV_STR + 8 * ni + g];
                uint32_t b1 = sv[(8 * kd + c + 4) * SV_STR + 8 * ni + g];
                mma8(o[ni], pa, b0, b1);
            }
        }
        __syncthreads();   // all warps done reading this stage before re-fill
    }

    // ---- finalize ----
    float inv0 = 1.f / l0r, inv1 = 1.f / l1r;
    size_t orow = (size_t)b * SEQ + q0 + 16 * w + g;
#pragma unroll
    for (int ni = 0; ni < 8; ni++) {
        int col = 8 * ni + 2 * c;
        *(float2*)&out[orow * HDIM + col] =
            make_float2(o[ni][0] * inv0, o[ni][1] * inv0);
        *(float2*)&out[(orow + 8) * HDIM + col] =
            make_float2(o[ni][2] * inv1, o[ni][3] * inv1);
    }
}

// ---------------------------------------------------------------------------
extern "C" void kernel_launch(void* const* d_in, const int* in_sizes, int n_in,
                              void* d_out, int out_size)
{
    const float* x  = (const float*)d_in[0];
    const float* Wq = (const float*)d_in[1];
    const float* bq = (const float*)d_in[2];
    const float* Wk = (const float*)d_in[3];
    const float* bk = (const float*)d_in[4];
    const float* Wv = (const float*)d_in[5];
    const float* bv = (const float*)d_in[6];
    float* out = (float*)d_out;

    qkv_kernel<<<(BATCH * SEQ) / 128, 512>>>(x, Wq, bq, Wk, bk, Wv, bv);

    cudaFuncSetAttribute(attn_kernel, cudaFuncAttributeMaxDynamicSharedMemorySize, ATT_SMEM);
    dim3 grid(SEQ / 64, BATCH);
    attn_kernel<<<grid, 128, ATT_SMEM>>>(out);
}

// round 11
// speedup vs baseline: 5.1863x; 1.5150x over previous
#include <cuda_runtime.h>
#include <cuda_fp16.h>
#include <cstdint>
#include <math.h>

#define BATCH 16
#define SEQ   2048
#define DMODEL 1024
#define HDIM  64
#define NQKV  192

// scratch: q (pre-scaled) | k | v as fp16, [B*S][192]
__device__ __half g_qkv[(size_t)BATCH * SEQ * NQKV];

__device__ __forceinline__ float ex2(float x) {
    float r;
    asm("ex2.approx.ftz.f32 %0, %1;" : "=f"(r) : "f"(x));
    return r;
}
__device__ __forceinline__ void cp16(uint32_t dst, const void* src) {
    asm volatile("cp.async.cg.shared.global [%0], [%1], 16;" :: "r"(dst), "l"(src));
}
__device__ __forceinline__ uint32_t packh2(float a, float b) {
    __half2 h = __floats2half2_rn(a, b);
    return *reinterpret_cast<uint32_t*>(&h);
}
// D += A(16x16) * B(16x8), fp16 inputs, fp32 accum
__device__ __forceinline__ void mma16(float* d, const uint32_t* a, uint32_t b0, uint32_t b1) {
    asm volatile(
        "mma.sync.aligned.m16n8k16.row.col.f32.f16.f16.f32 "
        "{%0,%1,%2,%3}, {%4,%5,%6,%7}, {%8,%9}, {%0,%1,%2,%3};\n"
        : "+f"(d[0]), "+f"(d[1]), "+f"(d[2]), "+f"(d[3])
        : "r"(a[0]), "r"(a[1]), "r"(a[2]), "r"(a[3]), "r"(b0), "r"(b1));
}
__device__ __forceinline__ void ldsm4(uint32_t& r0, uint32_t& r1, uint32_t& r2, uint32_t& r3, uint32_t a) {
    asm volatile("ldmatrix.sync.aligned.m8n8.x4.shared.b16 {%0,%1,%2,%3}, [%4];"
                 : "=r"(r0), "=r"(r1), "=r"(r2), "=r"(r3) : "r"(a));
}
__device__ __forceinline__ void ldsm4t(uint32_t& r0, uint32_t& r1, uint32_t& r2, uint32_t& r3, uint32_t a) {
    asm volatile("ldmatrix.sync.aligned.m8n8.x4.trans.shared.b16 {%0,%1,%2,%3}, [%4];"
                 : "=r"(r0), "=r"(r1), "=r"(r2), "=r"(r3) : "r"(a));
}

#define QSCALE (0.125f * 1.44269504088896340736f)   // 1/sqrt(64) * log2(e)

// ---------------------------------------------------------------------------
// Kernel 1: fused QKV projection, fp16 mma (m16n8k16).
// Block 128x192, 512 threads (16 warps: 4m x 4n, warp 32x48, mi=2 ni=6).
// Register-prefetch double buffering; frags via ldmatrix.
// Epilogue: +bias, q pre-scaled, store fp16.
// ---------------------------------------------------------------------------
#define SA_STR 24    // halves per row (48B, 16B-aligned for ldmatrix)
#define SB_STR 200   // halves per row (400B)

__global__ __launch_bounds__(512, 1) void qkv_kernel(
    const float* __restrict__ x,
    const float* __restrict__ Wq, const float* __restrict__ bq,
    const float* __restrict__ Wk, const float* __restrict__ bk,
    const float* __restrict__ Wv, const float* __restrict__ bv)
{
    __shared__ __half sA[128 * SA_STR];
    __shared__ __half sB[16 * SB_STR];
    __shared__ float sbias[NQKV];

    const int tid  = threadIdx.x;
    const int w    = tid >> 5;
    const int lane = tid & 31;
    const int g    = lane >> 2;
    const int c    = lane & 3;
    const int wm   = w >> 2;      // 0..3 (32-row group)
    const int wn   = w & 3;       // 0..3 (48-col group)
    const int m0   = blockIdx.x * 128;

    const uint32_t sAu = (uint32_t)__cvta_generic_to_shared(sA);
    const uint32_t sBu = (uint32_t)__cvta_generic_to_shared(sB);

    if (tid < NQKV)
        sbias[tid] = (tid < 64) ? bq[tid] : ((tid < 128) ? bk[tid - 64] : bv[tid - 128]);

    // ---- per-thread load slots ----
    const int a_row = tid >> 2;          // A: 128x16 = 512 float4, 1/thread
    const int a_c4  = (tid & 3) * 4;
    int b_row[2], b_c4[2];
    const float* b_src[2];
#pragma unroll
    for (int i = 0; i < 2; i++) {        // B: 16x192 = 768 float4
        int id = tid + i * 512;
        b_row[i] = (id / 48) & 15;
        b_c4[i]  = id % 48;
        int mm = b_c4[i] >> 4;
        int lc = (b_c4[i] & 15) * 4;
        const float* Wsrc = (mm == 0) ? Wq : ((mm == 1) ? Wk : Wv);
        b_src[i] = Wsrc + (size_t)b_row[i] * HDIM + lc;
    }
    const bool b2ok = (tid < 256);

    float acc[2][6][4];
#pragma unroll
    for (int mi = 0; mi < 2; mi++)
#pragma unroll
        for (int ni = 0; ni < 6; ni++)
#pragma unroll
            for (int r = 0; r < 4; r++) acc[mi][ni][r] = 0.f;

    float4 pa, pb0, pb1;
    pa  = *(const float4*)&x[(size_t)(m0 + a_row) * DMODEL + a_c4];
    pb0 = *(const float4*)(b_src[0]);
    if (b2ok) pb1 = *(const float4*)(b_src[1]);

    for (int kc = 0; kc < DMODEL / 16; kc++) {
        // ---- commit prefetched chunk (fp32 -> fp16 smem) ----
        *(uint2*)&sA[a_row * SA_STR + a_c4] =
            make_uint2(packh2(pa.x, pa.y), packh2(pa.z, pa.w));
        *(uint2*)&sB[b_row[0] * SB_STR + b_c4[0] * 4] =
            make_uint2(packh2(pb0.x, pb0.y), packh2(pb0.z, pb0.w));
        if (b2ok)
            *(uint2*)&sB[b_row[1] * SB_STR + b_c4[1] * 4] =
                make_uint2(packh2(pb1.x, pb1.y), packh2(pb1.z, pb1.w));

        // ---- prefetch next chunk ----
        if (kc + 1 < DMODEL / 16) {
            int kb = (kc + 1) * 16;
            pa  = *(const float4*)&x[(size_t)(m0 + a_row) * DMODEL + kb + a_c4];
            pb0 = *(const float4*)(b_src[0] + (size_t)kb * HDIM);
            if (b2ok) pb1 = *(const float4*)(b_src[1] + (size_t)kb * HDIM);
        }
        __syncthreads();

        // ---- frags via ldmatrix + 12 HMMA ----
        uint32_t a[2][4];
#pragma unroll
        for (int mi = 0; mi < 2; mi++) {
            int r0 = 32 * wm + 16 * mi;
            uint32_t ad = sAu + (uint32_t)((r0 + (lane & 15)) * (SA_STR * 2) + ((lane >> 4) & 1) * 16);
            ldsm4(a[mi][0], a[mi][1], a[mi][2], a[mi][3], ad);
        }
#pragma unroll
        for (int np = 0; np < 6; np += 2) {
            uint32_t b0, b1, b2, b3;
            uint32_t bd = sBu + (uint32_t)((lane & 15) * (SB_STR * 2) +
                                           (48 * wn + 8 * (np + (lane >> 4))) * 2);
            ldsm4t(b0, b1, b2, b3, bd);
            mma16(acc[0][np],     a[0], b0, b1);
            mma16(acc[1][np],     a[1], b0, b1);
            mma16(acc[0][np + 1], a[0], b2, b3);
            mma16(acc[1][np + 1], a[1], b2, b3);
        }
        __syncthreads();
    }

    // ---- epilogue: +bias, q*=QSCALE, fp16 store ----
#pragma unroll
    for (int mi = 0; mi < 2; mi++) {
        int r = m0 + 32 * wm + 16 * mi + g;
#pragma unroll
        for (int ni = 0; ni < 6; ni++) {
            int col = 48 * wn + 8 * ni + 2 * c;
            float b0f = sbias[col], b1f = sbias[col + 1];
            float sc = (col < 64) ? QSCALE : 1.0f;
            *(uint32_t*)&g_qkv[(size_t)r * NQKV + col] =
                packh2((acc[mi][ni][0] + b0f) * sc, (acc[mi][ni][1] + b1f) * sc);
            *(uint32_t*)&g_qkv[(size_t)(r + 8) * NQKV + col] =
                packh2((acc[mi][ni][2] + b0f) * sc, (acc[mi][ni][3] + b1f) * sc);
        }
    }
}

// ---------------------------------------------------------------------------
// Kernel 2: causal flash attention, fp16 mma (m16n8k16).
// Block: 64 q-rows, 128 threads (4 warps x 16 q-rows), kv tiles of 64.
// K/V via cp.async 2-stage double buffer (fp16, half the bytes of R7).
// K-frags: ldmatrix.x4; V-frags: ldmatrix.x4.trans; P: direct C->A repack.
// ---------------------------------------------------------------------------
#define SKV_ROW   144                     // bytes per K or V smem row (72 halves)
#define SK_BYTES  (64 * SKV_ROW)          // 9216
#define STAGE_B   (2 * SK_BYTES)          // 18432 (K then V)
#define ATT_SMEM  (2 * STAGE_B)           // 36864

__global__ __launch_bounds__(128, 4) void attn_kernel(float* __restrict__ out)
{
    extern __shared__ char dsm[];
    const uint32_t smem_u32 = (uint32_t)__cvta_generic_to_shared(dsm);

    const int tid  = threadIdx.x;
    const int lane = tid & 31;
    const int w    = tid >> 5;
    const int g    = lane >> 2;
    const int c    = lane & 3;
    const int b    = blockIdx.y;
    const int qi   = (int)gridDim.x - 1 - (int)blockIdx.x;   // long blocks first
    const int q0   = qi * 64;
    const size_t base = (size_t)b * SEQ * NQKV;

    // ---- issue tile 0 prefetch ----
    {
#pragma unroll
        for (int i = 0; i < 8; i++) {
            int id  = tid + i * 128;
            int row = id >> 4;
            int ch  = id & 15;
            const __half* src = g_qkv + base + (size_t)row * NQKV;
            if (ch < 8)
                cp16(smem_u32 + row * SKV_ROW + ch * 16, src + 64 + ch * 8);
            else
                cp16(smem_u32 + SK_BYTES + row * SKV_ROW + (ch - 8) * 16, src + 128 + (ch - 8) * 8);
        }
        asm volatile("cp.async.commit_group;" ::: "memory");
    }

    // ---- hoist Q frags (fp16, pre-scaled) ----
    uint32_t qa[4][4];
    {
        const __half* q0p = g_qkv + base + (size_t)(q0 + 16 * w + g) * NQKV;
        const __half* q1p = q0p + 8 * NQKV;
#pragma unroll
        for (int kd = 0; kd < 4; kd++) {
            qa[kd][0] = *(const uint32_t*)(q0p + 16 * kd + 2 * c);
            qa[kd][1] = *(const uint32_t*)(q1p + 16 * kd + 2 * c);
            qa[kd][2] = *(const uint32_t*)(q0p + 16 * kd + 2 * c + 8);
            qa[kd][3] = *(const uint32_t*)(q1p + 16 * kd + 2 * c + 8);
        }
    }

    float o[8][4];
#pragma unroll
    for (int ni = 0; ni < 8; ni++)
#pragma unroll
        for (int r = 0; r < 4; r++) o[ni][r] = 0.f;
    float m0r = -1e30f, m1r = -1e30f, l0r = 0.f, l1r = 0.f;

    for (int jt = 0; jt <= qi; jt++) {
        if (jt < qi) {
            int kn = (jt + 1) * 64;
            uint32_t sb = smem_u32 + ((jt + 1) & 1) * STAGE_B;
#pragma unroll
            for (int i = 0; i < 8; i++) {
                int id  = tid + i * 128;
                int row = id >> 4;
                int ch  = id & 15;
                const __half* src = g_qkv + base + (size_t)(kn + row) * NQKV;
                if (ch < 8)
                    cp16(sb + row * SKV_ROW + ch * 16, src + 64 + ch * 8);
                else
                    cp16(sb + SK_BYTES + row * SKV_ROW + (ch - 8) * 16, src + 128 + (ch - 8) * 8);
            }
            asm volatile("cp.async.commit_group;" ::: "memory");
            asm volatile("cp.async.wait_group 1;" ::: "memory");
        } else {
            asm volatile("cp.async.wait_group 0;" ::: "memory");
        }
        __syncthreads();

        const uint32_t skb = smem_u32 + (jt & 1) * STAGE_B;
        const uint32_t svb = skb + SK_BYTES;

        // ---- S = Q K^T ----
        float s[8][4];
#pragma unroll
        for (int ni = 0; ni < 8; ni++)
#pragma unroll
            for (int r = 0; r < 4; r++) s[ni][r] = 0.f;

#pragma unroll
        for (int kd = 0; kd < 4; kd++) {
#pragma unroll
            for (int p = 0; p < 8; p += 2) {
                uint32_t b0, b1, b2, b3;
                uint32_t ad = skb + (8 * (p + (lane >> 4)) + (lane & 7)) * SKV_ROW
                                  + 32 * kd + ((lane >> 3) & 1) * 16;
                ldsm4(b0, b1, b2, b3, ad);
                mma16(s[p],     qa[kd], b0, b1);
                mma16(s[p + 1], qa[kd], b2, b3);
            }
        }

        // ---- causal mask on diagonal tile ----
        if (jt == qi) {
            int rowg = q0 + 16 * w + g;
            int k0c  = jt * 64;
#pragma unroll
            for (int ni = 0; ni < 8; ni++) {
                int col = k0c + 8 * ni + 2 * c;
                if (col > rowg)         s[ni][0] = -1e30f;
                if (col + 1 > rowg)     s[ni][1] = -1e30f;
                if (col > rowg + 8)     s[ni][2] = -1e30f;
                if (col + 1 > rowg + 8) s[ni][3] = -1e30f;
            }
        }

        // ---- online softmax (rows g, g+8; quad-lane reductions) ----
        float lm0 = -1e30f, lm1 = -1e30f;
#pragma unroll
        for (int ni = 0; ni < 8; ni++) {
            lm0 = fmaxf(lm0, fmaxf(s[ni][0], s[ni][1]));
            lm1 = fmaxf(lm1, fmaxf(s[ni][2], s[ni][3]));
        }
        lm0 = fmaxf(lm0, __shfl_xor_sync(0xffffffffu, lm0, 1));
        lm0 = fmaxf(lm0, __shfl_xor_sync(0xffffffffu, lm0, 2));
        lm1 = fmaxf(lm1, __shfl_xor_sync(0xffffffffu, lm1, 1));
        lm1 = fmaxf(lm1, __shfl_xor_sync(0xffffffffu, lm1, 2));
        float mn0 = fmaxf(m0r, lm0), mn1 = fmaxf(m1r, lm1);
        float al0 = ex2(m0r - mn0), al1 = ex2(m1r - mn1);
        m0r = mn0; m1r = mn1;
        float ls0 = 0.f, ls1 = 0.f;
#pragma unroll
        for (int ni = 0; ni < 8; ni++) {
            s[ni][0] = ex2(s[ni][0] - mn0); ls0 += s[ni][0];
            s[ni][1] = ex2(s[ni][1] - mn0); ls0 += s[ni][1];
            s[ni][2] = ex2(s[ni][2] - mn1); ls1 += s[ni][2];
            s[ni][3] = ex2(s[ni][3] - mn1); ls1 += s[ni][3];
        }
        ls0 += __shfl_xor_sync(0xffffffffu, ls0, 1);
        ls0 += __shfl_xor_sync(0xffffffffu, ls0, 2);
        ls1 += __shfl_xor_sync(0xffffffffu, ls1, 1);
        ls1 += __shfl_xor_sync(0xffffffffu, ls1, 2);
        l0r = l0r * al0 + ls0;
        l1r = l1r * al1 + ls1;
#pragma unroll
        for (int ni = 0; ni < 8; ni++) {
            o[ni][0] *= al0; o[ni][1] *= al0;
            o[ni][2] *= al1; o[ni][3] *= al1;
        }

        // ---- O += P @ V  (direct fp16 C->A repack; V frags via ldmatrix.trans) ----
#pragma unroll
        for (int kd = 0; kd < 4; kd++) {
            uint32_t pa[4];
            pa[0] = packh2(s[2 * kd][0],     s[2 * kd][1]);
            pa[1] = packh2(s[2 * kd][2],     s[2 * kd][3]);
            pa[2] = packh2(s[2 * kd + 1][0], s[2 * kd + 1][1]);
            pa[3] = packh2(s[2 * kd + 1][2], s[2 * kd + 1][3]);
#pragma unroll
            for (int p = 0; p < 8; p += 2) {
                uint32_t b0, b1, b2, b3;
                uint32_t ad = svb + (16 * kd + (lane & 15)) * SKV_ROW
                                  + 16 * (p + (lane >> 4));
                ldsm4t(b0, b1, b2, b3, ad);
                mma16(o[p],     pa, b0, b1);
                mma16(o[p + 1], pa, b2, b3);
            }
        }
        __syncthreads();   // all warps done with this stage before re-fill
    }

    // ---- finalize ----
    float inv0 = 1.f / l0r, inv1 = 1.f / l1r;
    size_t orow = (size_t)b * SEQ + q0 + 16 * w + g;
#pragma unroll
    for (int ni = 0; ni < 8; ni++) {
        int col = 8 * ni + 2 * c;
        *(float2*)&out[orow * HDIM + col] =
            make_float2(o[ni][0] * inv0, o[ni][1] * inv0);
        *(float2*)&out[(orow + 8) * HDIM + col] =
            make_float2(o[ni][2] * inv1, o[ni][3] * inv1);
    }
}

// ---------------------------------------------------------------------------
extern "C" void kernel_launch(void* const* d_in, const int* in_sizes, int n_in,
                              void* d_out, int out_size)
{
    const float* x  = (const float*)d_in[0];
    const float* Wq = (const float*)d_in[1];
    const float* bq = (const float*)d_in[2];
    const float* Wk = (const float*)d_in[3];
    const float* bk = (const float*)d_in[4];
    const float* Wv = (const float*)d_in[5];
    const float* bv = (const float*)d_in[6];
    float* out = (float*)d_out;

    qkv_kernel<<<(BATCH * SEQ) / 128, 512>>>(x, Wq, bq, Wk, bk, Wv, bv);

    cudaFuncSetAttribute(attn_kernel, cudaFuncAttributeMaxDynamicSharedMemorySize, ATT_SMEM);
    dim3 grid(SEQ / 64, BATCH);
    attn_kernel<<<grid, 128, ATT_SMEM>>>(out);
}

// round 12
// speedup vs baseline: 5.7387x; 1.1065x over previous
#include <cuda_runtime.h>
#include <cuda_fp16.h>
#include <cstdint>
#include <math.h>

#define BATCH 16
#define SEQ   2048
#define DMODEL 1024
#define HDIM  64
#define NQKV  192

// scratch: q (pre-scaled) | k | v as fp16, [B*S][192]
__device__ __half g_qkv[(size_t)BATCH * SEQ * NQKV];

__device__ __forceinline__ float ex2(float x) {
    float r;
    asm("ex2.approx.ftz.f32 %0, %1;" : "=f"(r) : "f"(x));
    return r;
}
__device__ __forceinline__ void cp16(uint32_t dst, const void* src) {
    asm volatile("cp.async.cg.shared.global [%0], [%1], 16;" :: "r"(dst), "l"(src));
}
__device__ __forceinline__ uint32_t packh2(float a, float b) {
    __half2 h = __floats2half2_rn(a, b);
    return *reinterpret_cast<uint32_t*>(&h);
}
// D += A(16x16) * B(16x8), fp16 inputs, fp32 accum
__device__ __forceinline__ void mma16(float* d, const uint32_t* a, uint32_t b0, uint32_t b1) {
    asm volatile(
        "mma.sync.aligned.m16n8k16.row.col.f32.f16.f16.f32 "
        "{%0,%1,%2,%3}, {%4,%5,%6,%7}, {%8,%9}, {%0,%1,%2,%3};\n"
        : "+f"(d[0]), "+f"(d[1]), "+f"(d[2]), "+f"(d[3])
        : "r"(a[0]), "r"(a[1]), "r"(a[2]), "r"(a[3]), "r"(b0), "r"(b1));
}
__device__ __forceinline__ void ldsm4(uint32_t& r0, uint32_t& r1, uint32_t& r2, uint32_t& r3, uint32_t a) {
    asm volatile("ldmatrix.sync.aligned.m8n8.x4.shared.b16 {%0,%1,%2,%3}, [%4];"
                 : "=r"(r0), "=r"(r1), "=r"(r2), "=r"(r3) : "r"(a));
}
__device__ __forceinline__ void ldsm4t(uint32_t& r0, uint32_t& r1, uint32_t& r2, uint32_t& r3, uint32_t a) {
    asm volatile("ldmatrix.sync.aligned.m8n8.x4.trans.shared.b16 {%0,%1,%2,%3}, [%4];"
                 : "=r"(r0), "=r"(r1), "=r"(r2), "=r"(r3) : "r"(a));
}

#define QSCALE (0.125f * 1.44269504088896340736f)   // 1/sqrt(64) * log2(e)

// ---------------------------------------------------------------------------
// Kernel 1: fused QKV projection, fp16 mma (m16n8k16).
// Block 128x192, 512 threads (16 warps: 4m x 4n, warp 32x48, mi=2 ni=6).
// DOUBLE-BUFFERED smem + depth-2 register prefetch => 1 barrier per k-iter.
// ---------------------------------------------------------------------------
#define SA_STR 24    // halves per row
#define SB_STR 200   // halves per row

__global__ __launch_bounds__(512, 1) void qkv_kernel(
    const float* __restrict__ x,
    const float* __restrict__ Wq, const float* __restrict__ bq,
    const float* __restrict__ Wk, const float* __restrict__ bk,
    const float* __restrict__ Wv, const float* __restrict__ bv)
{
    __shared__ __half sA[2][128 * SA_STR];
    __shared__ __half sB[2][16 * SB_STR];
    __shared__ float sbias[NQKV];

    const int tid  = threadIdx.x;
    const int w    = tid >> 5;
    const int lane = tid & 31;
    const int g    = lane >> 2;
    const int c    = lane & 3;
    const int wm   = w >> 2;      // 0..3 (32-row group)
    const int wn   = w & 3;       // 0..3 (48-col group)
    const int m0   = blockIdx.x * 128;

    const uint32_t sAu[2] = { (uint32_t)__cvta_generic_to_shared(sA[0]),
                              (uint32_t)__cvta_generic_to_shared(sA[1]) };
    const uint32_t sBu[2] = { (uint32_t)__cvta_generic_to_shared(sB[0]),
                              (uint32_t)__cvta_generic_to_shared(sB[1]) };

    if (tid < NQKV)
        sbias[tid] = (tid < 64) ? bq[tid] : ((tid < 128) ? bk[tid - 64] : bv[tid - 128]);

    // ---- per-thread load slots ----
    const int a_row = tid >> 2;          // A: 128x16 = 512 float4, 1/thread
    const int a_c4  = (tid & 3) * 4;
    int b_row[2], b_c4[2];
    const float* b_src[2];
#pragma unroll
    for (int i = 0; i < 2; i++) {        // B: 16x192 = 768 float4
        int id = tid + i * 512;
        b_row[i] = (id / 48) & 15;
        b_c4[i]  = id % 48;
        int mm = b_c4[i] >> 4;
        int lc = (b_c4[i] & 15) * 4;
        const float* Wsrc = (mm == 0) ? Wq : ((mm == 1) ? Wk : Wv);
        b_src[i] = Wsrc + (size_t)b_row[i] * HDIM + lc;
    }
    const bool b2ok = (tid < 256);

    float acc[2][6][4];
#pragma unroll
    for (int mi = 0; mi < 2; mi++)
#pragma unroll
        for (int ni = 0; ni < 6; ni++)
#pragma unroll
            for (int r = 0; r < 4; r++) acc[mi][ni][r] = 0.f;

    // ---- depth-2 register prefetch: chunk 0 -> slot0, chunk 1 -> slot1 ----
    float4 pa[2], pb0[2], pb1[2];
#pragma unroll
    for (int i = 0; i < 2; i++) {
        int kb = i * 16;
        pa[i]  = *(const float4*)&x[(size_t)(m0 + a_row) * DMODEL + kb + a_c4];
        pb0[i] = *(const float4*)(b_src[0] + (size_t)kb * HDIM);
        if (b2ok) pb1[i] = *(const float4*)(b_src[1] + (size_t)kb * HDIM);
    }

    for (int kc = 0; kc < DMODEL / 16; kc++) {
        const int pp = kc & 1;
        // ---- commit slot pp to smem buffer pp (fp32 -> fp16) ----
        *(uint2*)&sA[pp][a_row * SA_STR + a_c4] =
            make_uint2(packh2(pa[pp].x, pa[pp].y), packh2(pa[pp].z, pa[pp].w));
        *(uint2*)&sB[pp][b_row[0] * SB_STR + b_c4[0] * 4] =
            make_uint2(packh2(pb0[pp].x, pb0[pp].y), packh2(pb0[pp].z, pb0[pp].w));
        if (b2ok)
            *(uint2*)&sB[pp][b_row[1] * SB_STR + b_c4[1] * 4] =
                make_uint2(packh2(pb1[pp].x, pb1[pp].y), packh2(pb1[pp].z, pb1[pp].w));

        // ---- refill slot pp with chunk kc+2 ----
        if (kc + 2 < DMODEL / 16) {
            int kb = (kc + 2) * 16;
            pa[pp]  = *(const float4*)&x[(size_t)(m0 + a_row) * DMODEL + kb + a_c4];
            pb0[pp] = *(const float4*)(b_src[0] + (size_t)kb * HDIM);
            if (b2ok) pb1[pp] = *(const float4*)(b_src[1] + (size_t)kb * HDIM);
        }
        __syncthreads();   // buffer pp fully written; prior readers of pp done 2 iters ago

        // ---- frags via ldmatrix + 12 HMMA (from buffer pp) ----
        uint32_t a[2][4];
#pragma unroll
        for (int mi = 0; mi < 2; mi++) {
            int r0 = 32 * wm + 16 * mi;
            uint32_t ad = sAu[pp] + (uint32_t)((r0 + (lane & 15)) * (SA_STR * 2) + ((lane >> 4) & 1) * 16);
            ldsm4(a[mi][0], a[mi][1], a[mi][2], a[mi][3], ad);
        }
#pragma unroll
        for (int np = 0; np < 6; np += 2) {
            uint32_t b0, b1, b2, b3;
            uint32_t bd = sBu[pp] + (uint32_t)((lane & 15) * (SB_STR * 2) +
                                               (48 * wn + 8 * (np + (lane >> 4))) * 2);
            ldsm4t(b0, b1, b2, b3, bd);
            mma16(acc[0][np],     a[0], b0, b1);
            mma16(acc[1][np],     a[1], b0, b1);
            mma16(acc[0][np + 1], a[0], b2, b3);
            mma16(acc[1][np + 1], a[1], b2, b3);
        }
    }

    // ---- epilogue: +bias, q*=QSCALE, fp16 store ----
#pragma unroll
    for (int mi = 0; mi < 2; mi++) {
        int r = m0 + 32 * wm + 16 * mi + g;
#pragma unroll
        for (int ni = 0; ni < 6; ni++) {
            int col = 48 * wn + 8 * ni + 2 * c;
            float b0f = sbias[col], b1f = sbias[col + 1];
            float sc = (col < 64) ? QSCALE : 1.0f;
            *(uint32_t*)&g_qkv[(size_t)r * NQKV + col] =
                packh2((acc[mi][ni][0] + b0f) * sc, (acc[mi][ni][1] + b1f) * sc);
            *(uint32_t*)&g_qkv[(size_t)(r + 8) * NQKV + col] =
                packh2((acc[mi][ni][2] + b0f) * sc, (acc[mi][ni][3] + b1f) * sc);
        }
    }
}

// ---------------------------------------------------------------------------
// Kernel 2: causal flash attention, fp16 mma (m16n8k16).
// Block: 64 q-rows, 128 threads (4 warps x 16 q-rows), kv tiles of 64.
// 3-STAGE cp.async ring, prefetch distance 1, always-commit => 1 barrier/iter.
// ---------------------------------------------------------------------------
#define SKV_ROW   144                     // bytes per K or V smem row (72 halves)
#define SK_BYTES  (64 * SKV_ROW)          // 9216
#define STAGE_B   (2 * SK_BYTES)          // 18432 (K then V)
#define ATT_SMEM  (3 * STAGE_B)           // 55296

__global__ __launch_bounds__(128, 4) void attn_kernel(float* __restrict__ out)
{
    extern __shared__ char dsm[];
    const uint32_t smem_u32 = (uint32_t)__cvta_generic_to_shared(dsm);

    const int tid  = threadIdx.x;
    const int lane = tid & 31;
    const int w    = tid >> 5;
    const int g    = lane >> 2;
    const int c    = lane & 3;
    const int b    = blockIdx.y;
    const int qi   = (int)gridDim.x - 1 - (int)blockIdx.x;   // long blocks first
    const int q0   = qi * 64;
    const size_t base = (size_t)b * SEQ * NQKV;

    // ---- issue tile 0 into stage 0 ----
    {
#pragma unroll
        for (int i = 0; i < 8; i++) {
            int id  = tid + i * 128;
            int row = id >> 4;
            int ch  = id & 15;
            const __half* src = g_qkv + base + (size_t)row * NQKV;
            if (ch < 8)
                cp16(smem_u32 + row * SKV_ROW + ch * 16, src + 64 + ch * 8);
            else
                cp16(smem_u32 + SK_BYTES + row * SKV_ROW + (ch - 8) * 16, src + 128 + (ch - 8) * 8);
        }
        asm volatile("cp.async.commit_group;" ::: "memory");
    }

    // ---- hoist Q frags (fp16, pre-scaled) ----
    uint32_t qa[4][4];
    {
        const __half* q0p = g_qkv + base + (size_t)(q0 + 16 * w + g) * NQKV;
        const __half* q1p = q0p + 8 * NQKV;
#pragma unroll
        for (int kd = 0; kd < 4; kd++) {
            qa[kd][0] = *(const uint32_t*)(q0p + 16 * kd + 2 * c);
            qa[kd][1] = *(const uint32_t*)(q1p + 16 * kd + 2 * c);
            qa[kd][2] = *(const uint32_t*)(q0p + 16 * kd + 2 * c + 8);
            qa[kd][3] = *(const uint32_t*)(q1p + 16 * kd + 2 * c + 8);
        }
    }

    float o[8][4];
#pragma unroll
    for (int ni = 0; ni < 8; ni++)
#pragma unroll
        for (int r = 0; r < 4; r++) o[ni][r] = 0.f;
    float m0r = -1e30f, m1r = -1e30f, l0r = 0.f, l1r = 0.f;

    for (int jt = 0; jt <= qi; jt++) {
        // ---- issue tile jt+1 into stage (jt+1)%3 (if any); always commit ----
        if (jt + 1 <= qi) {
            int kn = (jt + 1) * 64;
            int st = (jt + 1) % 3;
            uint32_t sb = smem_u32 + st * STAGE_B;
#pragma unroll
            for (int i = 0; i < 8; i++) {
                int id  = tid + i * 128;
                int row = id >> 4;
                int ch  = id & 15;
                const __half* src = g_qkv + base + (size_t)(kn + row) * NQKV;
                if (ch < 8)
                    cp16(sb + row * SKV_ROW + ch * 16, src + 64 + ch * 8);
                else
                    cp16(sb + SK_BYTES + row * SKV_ROW + (ch - 8) * 16, src + 128 + (ch - 8) * 8);
            }
        }
        asm volatile("cp.async.commit_group;" ::: "memory");
        asm volatile("cp.async.wait_group 1;" ::: "memory");   // tile jt complete
        __syncthreads();                                        // one barrier per iter

        const uint32_t skb = smem_u32 + (jt % 3) * STAGE_B;
        const uint32_t svb = skb + SK_BYTES;

        // ---- S = Q K^T ----
        float s[8][4];
#pragma unroll
        for (int ni = 0; ni < 8; ni++)
#pragma unroll
            for (int r = 0; r < 4; r++) s[ni][r] = 0.f;

#pragma unroll
        for (int kd = 0; kd < 4; kd++) {
#pragma unroll
            for (int p = 0; p < 8; p += 2) {
                uint32_t b0, b1, b2, b3;
                uint32_t ad = skb + (8 * (p + (lane >> 4)) + (lane & 7)) * SKV_ROW
                                  + 32 * kd + ((lane >> 3) & 1) * 16;
                ldsm4(b0, b1, b2, b3, ad);
                mma16(s[p],     qa[kd], b0, b1);
                mma16(s[p + 1], qa[kd], b2, b3);
            }
        }

        // ---- causal mask on diagonal tile ----
        if (jt == qi) {
            int rowg = q0 + 16 * w + g;
            int k0c  = jt * 64;
#pragma unroll
            for (int ni = 0; ni < 8; ni++) {
                int col = k0c + 8 * ni + 2 * c;
                if (col > rowg)         s[ni][0] = -1e30f;
                if (col + 1 > rowg)     s[ni][1] = -1e30f;
                if (col > rowg + 8)     s[ni][2] = -1e30f;
                if (col + 1 > rowg + 8) s[ni][3] = -1e30f;
            }
        }

        // ---- online softmax (rows g, g+8; quad-lane reductions) ----
        float lm0 = -1e30f, lm1 = -1e30f;
#pragma unroll
        for (int ni = 0; ni < 8; ni++) {
            lm0 = fmaxf(lm0, fmaxf(s[ni][0], s[ni][1]));
            lm1 = fmaxf(lm1, fmaxf(s[ni][2], s[ni][3]));
        }
        lm0 = fmaxf(lm0, __shfl_xor_sync(0xffffffffu, lm0, 1));
        lm0 = fmaxf(lm0, __shfl_xor_sync(0xffffffffu, lm0, 2));
        lm1 = fmaxf(lm1, __shfl_xor_sync(0xffffffffu, lm1, 1));
        lm1 = fmaxf(lm1, __shfl_xor_sync(0xffffffffu, lm1, 2));
        float mn0 = fmaxf(m0r, lm0), mn1 = fmaxf(m1r, lm1);
        float al0 = ex2(m0r - mn0), al1 = ex2(m1r - mn1);
        m0r = mn0; m1r = mn1;
        float ls0 = 0.f, ls1 = 0.f;
#pragma unroll
        for (int ni = 0; ni < 8; ni++) {
            s[ni][0] = ex2(s[ni][0] - mn0); ls0 += s[ni][0];
            s[ni][1] = ex2(s[ni][1] - mn0); ls0 += s[ni][1];
            s[ni][2] = ex2(s[ni][2] - mn1); ls1 += s[ni][2];
            s[ni][3] = ex2(s[ni][3] - mn1); ls1 += s[ni][3];
        }
        ls0 += __shfl_xor_sync(0xffffffffu, ls0, 1);
        ls0 += __shfl_xor_sync(0xffffffffu, ls0, 2);
        ls1 += __shfl_xor_sync(0xffffffffu, ls1, 1);
        ls1 += __shfl_xor_sync(0xffffffffu, ls1, 2);
        l0r = l0r * al0 + ls0;
        l1r = l1r * al1 + ls1;
#pragma unroll
        for (int ni = 0; ni < 8; ni++) {
            o[ni][0] *= al0; o[ni][1] *= al0;
            o[ni][2] *= al1; o[ni][3] *= al1;
        }

        // ---- O += P @ V  (direct fp16 C->A repack; V frags via ldmatrix.trans) ----
#pragma unroll
        for (int kd = 0; kd < 4; kd++) {
            uint32_t pa[4];
            pa[0] = packh2(s[2 * kd][0],     s[2 * kd][1]);
            pa[1] = packh2(s[2 * kd][2],     s[2 * kd][3]);
            pa[2] = packh2(s[2 * kd + 1][0], s[2 * kd + 1][1]);
            pa[3] = packh2(s[2 * kd + 1][2], s[2 * kd + 1][3]);
#pragma unroll
            for (int p = 0; p < 8; p += 2) {
                uint32_t b0, b1, b2, b3;
                uint32_t ad = svb + (16 * kd + (lane & 15)) * SKV_ROW
                                  + 16 * (p + (lane >> 4));
                ldsm4t(b0, b1, b2, b3, ad);
                mma16(o[p],     pa, b0, b1);
                mma16(o[p + 1], pa, b2, b3);
            }
        }
    }

    // ---- finalize ----
    float inv0 = 1.f / l0r, inv1 = 1.f / l1r;
    size_t orow = (size_t)b * SEQ + q0 + 16 * w + g;
#pragma unroll
    for (int ni = 0; ni < 8; ni++) {
        int col = 8 * ni + 2 * c;
        *(float2*)&out[orow * HDIM + col] =
            make_float2(o[ni][0] * inv0, o[ni][1] * inv0);
        *(float2*)&out[(orow + 8) * HDIM + col] =
            make_float2(o[ni][2] * inv1, o[ni][3] * inv1);
    }
}

// ---------------------------------------------------------------------------
extern "C" void kernel_launch(void* const* d_in, const int* in_sizes, int n_in,
                              void* d_out, int out_size)
{
    const float* x  = (const float*)d_in[0];
    const float* Wq = (const float*)d_in[1];
    const float* bq = (const float*)d_in[2];
    const float* Wk = (const float*)d_in[3];
    const float* bk = (const float*)d_in[4];
    const float* Wv = (const float*)d_in[5];
    const float* bv = (const float*)d_in[6];
    float* out = (float*)d_out;

    qkv_kernel<<<(BATCH * SEQ) / 128, 512>>>(x, Wq, bq, Wk, bk, Wv, bv);

    cudaFuncSetAttribute(attn_kernel, cudaFuncAttributeMaxDynamicSharedMemorySize, ATT_SMEM);
    dim3 grid(SEQ / 64, BATCH);
    attn_kernel<<<grid, 128, ATT_SMEM>>>(out);
}

// round 13
// speedup vs baseline: 6.0558x; 1.0553x over previous
#include <cuda_runtime.h>
#include <cuda_fp16.h>
#include <cstdint>
#include <math.h>

#define BATCH 16
#define SEQ   2048
#define DMODEL 1024
#define HDIM  64
#define NQKV  192

// scratch: q (pre-scaled) | k | v as fp16, [B*S][192]
__device__ __half g_qkv[(size_t)BATCH * SEQ * NQKV];

__device__ __forceinline__ float ex2(float x) {
    float r;
    asm("ex2.approx.ftz.f32 %0, %1;" : "=f"(r) : "f"(x));
    return r;
}
__device__ __forceinline__ void cp16(uint32_t dst, const void* src) {
    asm volatile("cp.async.cg.shared.global [%0], [%1], 16;" :: "r"(dst), "l"(src));
}
__device__ __forceinline__ uint32_t packh2(float a, float b) {
    __half2 h = __floats2half2_rn(a, b);
    return *reinterpret_cast<uint32_t*>(&h);
}
__device__ __forceinline__ void mma16(float* d, const uint32_t* a, uint32_t b0, uint32_t b1) {
    asm volatile(
        "mma.sync.aligned.m16n8k16.row.col.f32.f16.f16.f32 "
        "{%0,%1,%2,%3}, {%4,%5,%6,%7}, {%8,%9}, {%0,%1,%2,%3};\n"
        : "+f"(d[0]), "+f"(d[1]), "+f"(d[2]), "+f"(d[3])
        : "r"(a[0]), "r"(a[1]), "r"(a[2]), "r"(a[3]), "r"(b0), "r"(b1));
}
__device__ __forceinline__ void ldsm4(uint32_t& r0, uint32_t& r1, uint32_t& r2, uint32_t& r3, uint32_t a) {
    asm volatile("ldmatrix.sync.aligned.m8n8.x4.shared.b16 {%0,%1,%2,%3}, [%4];"
                 : "=r"(r0), "=r"(r1), "=r"(r2), "=r"(r3) : "r"(a));
}
__device__ __forceinline__ void ldsm4t(uint32_t& r0, uint32_t& r1, uint32_t& r2, uint32_t& r3, uint32_t a) {
    asm volatile("ldmatrix.sync.aligned.m8n8.x4.trans.shared.b16 {%0,%1,%2,%3}, [%4];"
                 : "=r"(r0), "=r"(r1), "=r"(r2), "=r"(r3) : "r"(a));
}

#define QSCALE (0.125f * 1.44269504088896340736f)   // 1/sqrt(64) * log2(e)

// ---------------------------------------------------------------------------
// Kernel 1: fused QKV projection, fp16 mma (m16n8k16).
// Block 64x192, 256 threads (8 warps: 2m x 4n, warp 32x48, mi=2 ni=6).
// 2 CTAs/SM. Double-buffered smem + depth-2 register prefetch, 1 barrier/iter.
// ---------------------------------------------------------------------------
#define SA_STR 24    // halves per row
#define SB_STR 200   // halves per row

__global__ __launch_bounds__(256, 2) void qkv_kernel(
    const float* __restrict__ x,
    const float* __restrict__ Wq, const float* __restrict__ bq,
    const float* __restrict__ Wk, const float* __restrict__ bk,
    const float* __restrict__ Wv, const float* __restrict__ bv)
{
    __shared__ __half sA[2][64 * SA_STR];
    __shared__ __half sB[2][16 * SB_STR];
    __shared__ float sbias[NQKV];

    const int tid  = threadIdx.x;
    const int w    = tid >> 5;
    const int lane = tid & 31;
    const int g    = lane >> 2;
    const int c    = lane & 3;
    const int wm   = w >> 2;      // 0..1 (32-row group)
    const int wn   = w & 3;       // 0..3 (48-col group)
    const int m0   = blockIdx.x * 64;

    const uint32_t sAu[2] = { (uint32_t)__cvta_generic_to_shared(sA[0]),
                              (uint32_t)__cvta_generic_to_shared(sA[1]) };
    const uint32_t sBu[2] = { (uint32_t)__cvta_generic_to_shared(sB[0]),
                              (uint32_t)__cvta_generic_to_shared(sB[1]) };

    if (tid < NQKV)
        sbias[tid] = (tid < 64) ? bq[tid] : ((tid < 128) ? bk[tid - 64] : bv[tid - 128]);

    // ---- per-thread load slots ----
    const int a_row = tid >> 2;          // A: 64x16 = 256 float4, 1/thread
    const int a_c4  = (tid & 3) * 4;
    int b_row[3], b_c4[3];
    const float* b_src[3];
#pragma unroll
    for (int i = 0; i < 3; i++) {        // B: 16x192 = 768 float4, 3/thread
        int id = tid + i * 256;
        b_row[i] = (id / 48) & 15;
        b_c4[i]  = id % 48;
        int mm = b_c4[i] >> 4;
        int lc = (b_c4[i] & 15) * 4;
        const float* Wsrc = (mm == 0) ? Wq : ((mm == 1) ? Wk : Wv);
        b_src[i] = Wsrc + (size_t)b_row[i] * HDIM + lc;
    }

    float acc[2][6][4];
#pragma unroll
    for (int mi = 0; mi < 2; mi++)
#pragma unroll
        for (int ni = 0; ni < 6; ni++)
#pragma unroll
            for (int r = 0; r < 4; r++) acc[mi][ni][r] = 0.f;

    // ---- depth-2 register prefetch ----
    float4 pa[2], pb[2][3];
#pragma unroll
    for (int i = 0; i < 2; i++) {
        int kb = i * 16;
        pa[i] = *(const float4*)&x[(size_t)(m0 + a_row) * DMODEL + kb + a_c4];
#pragma unroll
        for (int j = 0; j < 3; j++)
            pb[i][j] = *(const float4*)(b_src[j] + (size_t)kb * HDIM);
    }

    for (int kc = 0; kc < DMODEL / 16; kc++) {
        const int pp = kc & 1;
        // ---- commit slot pp to smem buffer pp (fp32 -> fp16) ----
        *(uint2*)&sA[pp][a_row * SA_STR + a_c4] =
            make_uint2(packh2(pa[pp].x, pa[pp].y), packh2(pa[pp].z, pa[pp].w));
#pragma unroll
        for (int j = 0; j < 3; j++)
            *(uint2*)&sB[pp][b_row[j] * SB_STR + b_c4[j] * 4] =
                make_uint2(packh2(pb[pp][j].x, pb[pp][j].y), packh2(pb[pp][j].z, pb[pp][j].w));

        // ---- refill slot pp with chunk kc+2 ----
        if (kc + 2 < DMODEL / 16) {
            int kb = (kc + 2) * 16;
            pa[pp] = *(const float4*)&x[(size_t)(m0 + a_row) * DMODEL + kb + a_c4];
#pragma unroll
            for (int j = 0; j < 3; j++)
                pb[pp][j] = *(const float4*)(b_src[j] + (size_t)kb * HDIM);
        }
        __syncthreads();

        // ---- frags via ldmatrix + 12 HMMA ----
        uint32_t a[2][4];
#pragma unroll
        for (int mi = 0; mi < 2; mi++) {
            int r0 = 32 * wm + 16 * mi;
            uint32_t ad = sAu[pp] + (uint32_t)((r0 + (lane & 15)) * (SA_STR * 2) + ((lane >> 4) & 1) * 16);
            ldsm4(a[mi][0], a[mi][1], a[mi][2], a[mi][3], ad);
        }
#pragma unroll
        for (int np = 0; np < 6; np += 2) {
            uint32_t b0, b1, b2, b3;
            uint32_t bd = sBu[pp] + (uint32_t)((lane & 15) * (SB_STR * 2) +
                                               (48 * wn + 8 * (np + (lane >> 4))) * 2);
            ldsm4t(b0, b1, b2, b3, bd);
            mma16(acc[0][np],     a[0], b0, b1);
            mma16(acc[1][np],     a[1], b0, b1);
            mma16(acc[0][np + 1], a[0], b2, b3);
            mma16(acc[1][np + 1], a[1], b2, b3);
        }
    }

    // ---- epilogue: +bias, q*=QSCALE, fp16 store ----
#pragma unroll
    for (int mi = 0; mi < 2; mi++) {
        int r = m0 + 32 * wm + 16 * mi + g;
#pragma unroll
        for (int ni = 0; ni < 6; ni++) {
            int col = 48 * wn + 8 * ni + 2 * c;
            float b0f = sbias[col], b1f = sbias[col + 1];
            float sc = (col < 64) ? QSCALE : 1.0f;
            *(uint32_t*)&g_qkv[(size_t)r * NQKV + col] =
                packh2((acc[mi][ni][0] + b0f) * sc, (acc[mi][ni][1] + b1f) * sc);
            *(uint32_t*)&g_qkv[(size_t)(r + 8) * NQKV + col] =
                packh2((acc[mi][ni][2] + b0f) * sc, (acc[mi][ni][3] + b1f) * sc);
        }
    }
}

// ---------------------------------------------------------------------------
// Kernel 2: causal flash attention, fp16 mma, softmax pipelined behind PV.
// Schedule per iter: S'(jt+1)-mma -> PV(jt)-mma -> softmax(jt+1).
// The softmax scalar/MUFU chain hides under the in-flight PV HMMAs.
// 3-stage cp.async ring; 1 wait + 1 barrier per iteration.
// ---------------------------------------------------------------------------
#define SKV_ROW   144
#define SK_BYTES  (64 * SKV_ROW)
#define STAGE_B   (2 * SK_BYTES)
#define ATT_SMEM  (3 * STAGE_B)           // 55296

__device__ __forceinline__ void issue_tile(uint32_t sb, const __half* srcbase, int tid) {
#pragma unroll
    for (int i = 0; i < 8; i++) {
        int id  = tid + i * 128;
        int row = id >> 4;
        int ch  = id & 15;
        const __half* src = srcbase + (size_t)row * NQKV;
        if (ch < 8)
            cp16(sb + row * SKV_ROW + ch * 16, src + 64 + ch * 8);
        else
            cp16(sb + SK_BYTES + row * SKV_ROW + (ch - 8) * 16, src + 128 + (ch - 8) * 8);
    }
}

__device__ __forceinline__ void qk_mma(float s[8][4], const uint32_t qa[4][4],
                                       uint32_t skb, int lane) {
#pragma unroll
    for (int ni = 0; ni < 8; ni++)
#pragma unroll
        for (int r = 0; r < 4; r++) s[ni][r] = 0.f;
#pragma unroll
    for (int kd = 0; kd < 4; kd++) {
#pragma unroll
        for (int p = 0; p < 8; p += 2) {
            uint32_t b0, b1, b2, b3;
            uint32_t ad = skb + (8 * (p + (lane >> 4)) + (lane & 7)) * SKV_ROW
                              + 32 * kd + ((lane >> 3) & 1) * 16;
            ldsm4(b0, b1, b2, b3, ad);
            mma16(s[p],     qa[kd], b0, b1);
            mma16(s[p + 1], qa[kd], b2, b3);
        }
    }
}

__device__ __forceinline__ void pv_mma(float o[8][4], const uint32_t pp[4][4],
                                       uint32_t svb, int lane) {
#pragma unroll
    for (int kd = 0; kd < 4; kd++) {
#pragma unroll
        for (int p = 0; p < 8; p += 2) {
            uint32_t b0, b1, b2, b3;
            uint32_t ad = svb + (16 * kd + (lane & 15)) * SKV_ROW
                              + 16 * (p + (lane >> 4));
            ldsm4t(b0, b1, b2, b3, ad);
            mma16(o[p],     pp[kd], b0, b1);
            mma16(o[p + 1], pp[kd], b2, b3);
        }
    }
}

__device__ __forceinline__ void mask_diag(float s[8][4], int rowg, int k0c, int c) {
#pragma unroll
    for (int ni = 0; ni < 8; ni++) {
        int col = k0c + 8 * ni + 2 * c;
        if (col > rowg)         s[ni][0] = -1e30f;
        if (col + 1 > rowg)     s[ni][1] = -1e30f;
        if (col > rowg + 8)     s[ni][2] = -1e30f;
        if (col + 1 > rowg + 8) s[ni][3] = -1e30f;
    }
}

// online softmax on s; rescales o; packs P into pp
__device__ __forceinline__ void softmax_pack(float s[8][4], float o[8][4],
    float& m0r, float& m1r, float& l0r, float& l1r, uint32_t pp[4][4])
{
    float lm0 = -1e30f, lm1 = -1e30f;
#pragma unroll
    for (int ni = 0; ni < 8; ni++) {
        lm0 = fmaxf(lm0, fmaxf(s[ni][0], s[ni][1]));
        lm1 = fmaxf(lm1, fmaxf(s[ni][2], s[ni][3]));
    }
    lm0 = fmaxf(lm0, __shfl_xor_sync(0xffffffffu, lm0, 1));
    lm0 = fmaxf(lm0, __shfl_xor_sync(0xffffffffu, lm0, 2));
    lm1 = fmaxf(lm1, __shfl_xor_sync(0xffffffffu, lm1, 1));
    lm1 = fmaxf(lm1, __shfl_xor_sync(0xffffffffu, lm1, 2));
    float mn0 = fmaxf(m0r, lm0), mn1 = fmaxf(m1r, lm1);
    float al0 = ex2(m0r - mn0), al1 = ex2(m1r - mn1);
    m0r = mn0; m1r = mn1;
    float ls0 = 0.f, ls1 = 0.f;
#pragma unroll
    for (int ni = 0; ni < 8; ni++) {
        s[ni][0] = ex2(s[ni][0] - mn0); ls0 += s[ni][0];
        s[ni][1] = ex2(s[ni][1] - mn0); ls0 += s[ni][1];
        s[ni][2] = ex2(s[ni][2] - mn1); ls1 += s[ni][2];
        s[ni][3] = ex2(s[ni][3] - mn1); ls1 += s[ni][3];
    }
    ls0 += __shfl_xor_sync(0xffffffffu, ls0, 1);
    ls0 += __shfl_xor_sync(0xffffffffu, ls0, 2);
    ls1 += __shfl_xor_sync(0xffffffffu, ls1, 1);
    ls1 += __shfl_xor_sync(0xffffffffu, ls1, 2);
    l0r = l0r * al0 + ls0;
    l1r = l1r * al1 + ls1;
#pragma unroll
    for (int ni = 0; ni < 8; ni++) {
        o[ni][0] *= al0; o[ni][1] *= al0;
        o[ni][2] *= al1; o[ni][3] *= al1;
    }
#pragma unroll
    for (int kd = 0; kd < 4; kd++) {
        pp[kd][0] = packh2(s[2 * kd][0],     s[2 * kd][1]);
        pp[kd][1] = packh2(s[2 * kd][2],     s[2 * kd][3]);
        pp[kd][2] = packh2(s[2 * kd + 1][0], s[2 * kd + 1][1]);
        pp[kd][3] = packh2(s[2 * kd + 1][2], s[2 * kd + 1][3]);
    }
}

__global__ __launch_bounds__(128, 3) void attn_kernel(float* __restrict__ out)
{
    extern __shared__ char dsm[];
    const uint32_t smem_u32 = (uint32_t)__cvta_generic_to_shared(dsm);

    const int tid  = threadIdx.x;
    const int lane = tid & 31;
    const int w    = tid >> 5;
    const int g    = lane >> 2;
    const int c    = lane & 3;
    const int b    = blockIdx.y;
    const int qi   = (int)gridDim.x - 1 - (int)blockIdx.x;   // long blocks first
    const int q0   = qi * 64;
    const size_t base = (size_t)b * SEQ * NQKV;
    const int rowg = q0 + 16 * w + g;

    // ---- prologue: tiles 0 and 1 into stages 0,1 ----
    issue_tile(smem_u32, g_qkv + base, tid);
    asm volatile("cp.async.commit_group;" ::: "memory");
    if (qi >= 1)
        issue_tile(smem_u32 + STAGE_B, g_qkv + base + (size_t)64 * NQKV, tid);
    asm volatile("cp.async.commit_group;" ::: "memory");

    // ---- hoist Q frags (fp16, pre-scaled) ----
    uint32_t qa[4][4];
    {
        const __half* q0p = g_qkv + base + (size_t)(q0 + 16 * w + g) * NQKV;
        const __half* q1p = q0p + 8 * NQKV;
#pragma unroll
        for (int kd = 0; kd < 4; kd++) {
            qa[kd][0] = *(const uint32_t*)(q0p + 16 * kd + 2 * c);
            qa[kd][1] = *(const uint32_t*)(q1p + 16 * kd + 2 * c);
            qa[kd][2] = *(const uint32_t*)(q0p + 16 * kd + 2 * c + 8);
            qa[kd][3] = *(const uint32_t*)(q1p + 16 * kd + 2 * c + 8);
        }
    }

    float o[8][4];
#pragma unroll
    for (int ni = 0; ni < 8; ni++)
#pragma unroll
        for (int r = 0; r < 4; r++) o[ni][r] = 0.f;
    float m0r = -1e30f, m1r = -1e30f, l0r = 0.f, l1r = 0.f;

    float s[8][4];
    uint32_t pp[4][4];

    // ---- first S + softmax (tile 0) ----
    asm volatile("cp.async.wait_group 1;" ::: "memory");   // tile 0 done
    __syncthreads();
    qk_mma(s, qa, smem_u32, lane);
    if (qi == 0) mask_diag(s, rowg, 0, c);
    softmax_pack(s, o, m0r, m1r, l0r, l1r, pp);

    // ---- pipelined mainloop ----
    for (int jt = 0; jt < qi; jt++) {
        asm volatile("cp.async.wait_group 0;" ::: "memory");   // tiles <= jt+1 done
        __syncthreads();                                        // stage (jt+2)%3 free
        if (jt + 2 <= qi)
            issue_tile(smem_u32 + ((jt + 2) % 3) * STAGE_B,
                       g_qkv + base + (size_t)((jt + 2) * 64) * NQKV, tid);
        asm volatile("cp.async.commit_group;" ::: "memory");

        const uint32_t sk1 = smem_u32 + ((jt + 1) % 3) * STAGE_B;   // K of tile jt+1
        const uint32_t sv0 = smem_u32 + (jt % 3) * STAGE_B + SK_BYTES; // V of tile jt

        qk_mma(s, qa, sk1, lane);          // tensor: S'(jt+1)
        pv_mma(o, pp, sv0, lane);          // tensor: PV(jt) — keeps pipe busy
        if (jt + 1 == qi) mask_diag(s, rowg, (jt + 1) * 64, c);
        softmax_pack(s, o, m0r, m1r, l0r, l1r, pp);   // scalar chain hides under PV
    }

    // ---- tail: PV on the last tile ----
    {
        const uint32_t sv = smem_u32 + (qi % 3) * STAGE_B + SK_BYTES;
        pv_mma(o, pp, sv, lane);
    }

    // ---- finalize ----
    float inv0 = 1.f / l0r, inv1 = 1.f / l1r;
    size_t orow = (size_t)b * SEQ + q0 + 16 * w + g;
#pragma unroll
    for (int ni = 0; ni < 8; ni++) {
        int col = 8 * ni + 2 * c;
        *(float2*)&out[orow * HDIM + col] =
            make_float2(o[ni][0] * inv0, o[ni][1] * inv0);
        *(float2*)&out[(orow + 8) * HDIM + col] =
            make_float2(o[ni][2] * inv1, o[ni][3] * inv1);
    }
}

// ---------------------------------------------------------------------------
extern "C" void kernel_launch(void* const* d_in, const int* in_sizes, int n_in,
                              void* d_out, int out_size)
{
    const float* x  = (const float*)d_in[0];
    const float* Wq = (const float*)d_in[1];
    const float* bq = (const float*)d_in[2];
    const float* Wk = (const float*)d_in[3];
    const float* bk = (const float*)d_in[4];
    const float* Wv = (const float*)d_in[5];
    const float* bv = (const float*)d_in[6];
    float* out = (float*)d_out;

    qkv_kernel<<<(BATCH * SEQ) / 64, 256>>>(x, Wq, bq, Wk, bk, Wv, bv);

    cudaFuncSetAttribute(attn_kernel, cudaFuncAttributeMaxDynamicSharedMemorySize, ATT_SMEM);
    dim3 grid(SEQ / 64, BATCH);
    attn_kernel<<<grid, 128, ATT_SMEM>>>(out);
}